// round 5
// baseline (speedup 1.0000x reference)
#include <cuda_runtime.h>
#include <cuda_fp16.h>
#include <cstdint>

#define HW    4096
#define CH    256
#define BATCH 4

// fp16 operands / activations
__device__ __half g_xh [2ull * BATCH * HW * CH];          // LN output [side][p][c]
__device__ __half g_wh [1024ull * 256];                   // [Wq|Wk|Wv|Wo]^T: [n][k]
__device__ __half g_qh [2ull * BATCH * HW * CH];          // [z][p][c]
__device__ __half g_kh [2ull * BATCH * HW * CH];          // [z][p][c]
__device__ __half g_vth[2ull * BATCH * HW * CH];          // V^T: [z][c][m]
__device__ __half g_eh [2ull * BATCH * HW * HW];          // E then P (in place)
__device__ __half g_oh [2ull * BATCH * HW * CH];          // PV output fp16 [side][p][c]

// ---------------------------------------------------------------------------
// low-level helpers
// ---------------------------------------------------------------------------
__device__ __forceinline__ uint32_t smem_u32(const void* p) {
    uint32_t a;
    asm("{ .reg .u64 t; cvta.to.shared.u64 t, %1; cvt.u32.u64 %0, t; }"
        : "=r"(a) : "l"(p));
    return a;
}

__device__ __forceinline__ void mma16816(float (&c)[4], const uint32_t (&a)[4],
                                         uint32_t b0, uint32_t b1) {
    asm volatile(
        "mma.sync.aligned.m16n8k16.row.col.f32.f16.f16.f32 "
        "{%0,%1,%2,%3}, {%4,%5,%6,%7}, {%8,%9}, {%0,%1,%2,%3};"
        : "+f"(c[0]), "+f"(c[1]), "+f"(c[2]), "+f"(c[3])
        : "r"(a[0]), "r"(a[1]), "r"(a[2]), "r"(a[3]), "r"(b0), "r"(b1));
}

__device__ __forceinline__ void ldsm4(uint32_t (&r)[4], uint32_t addr) {
    asm volatile("ldmatrix.sync.aligned.m8n8.x4.shared.b16 {%0,%1,%2,%3}, [%4];"
        : "=r"(r[0]), "=r"(r[1]), "=r"(r[2]), "=r"(r[3]) : "r"(addr));
}

#define CP16(s, g) \
    asm volatile("cp.async.cg.shared.global [%0], [%1], 16;" :: "r"(s), "l"(g))
#define CP_COMMIT() asm volatile("cp.async.commit_group;")
#define CP_WAIT2()  asm volatile("cp.async.wait_group 2;")

// ---------------------------------------------------------------------------
// GEMM core: CTA 128x256, k-chunk 32 halfs, 4-stage cp.async pipeline,
// ldmatrix fragments. 256 threads = 8 warps (2m x 4n), warp tile 64x64.
// smem stage: A 128 rows x 80B + B 256 rows x 80B = 30720 B; 4 stages = 120 KB.
// 1 CTA/SM (128 acc regs/thread).
// ---------------------------------------------------------------------------
#define STG_B    30720
#define SMEM_MMA 122880

template <int NCH>
__device__ __forceinline__ void gemm_core(const __half* __restrict__ Ag,
                                          const __half* __restrict__ Bg,
                                          int ldA, int ldB, uint32_t smb,
                                          float (&acc)[4][8][4]) {
    const int tid  = threadIdx.x;
    const int lane = tid & 31, wid = tid >> 5;
    const int wm = wid >> 2, wn = wid & 3;

    const int lr = tid >> 2;                 // load row 0..63
    const __half* agp = Ag + (size_t)lr * ldA + (tid & 3) * 8;
    const __half* bgp = Bg + (size_t)lr * ldB + (tid & 3) * 8;
    const size_t a64 = (size_t)64 * ldA, b64 = (size_t)64 * ldB;

    const uint32_t sA = smb + lr * 80 + (tid & 3) * 16;
    const uint32_t sB = sA + 10240;          // A region = 128*80 = 10240 B

    auto issue = [&](int s, int c) {
        const uint32_t off = s * STG_B;
        const __half* a0 = agp + (size_t)c * 32;
        const __half* b0 = bgp + (size_t)c * 32;
        CP16(sA + off,           a0);
        CP16(sA + off + 64 * 80, a0 + a64);
        CP16(sB + off,            b0);
        CP16(sB + off +  64 * 80, b0 + b64);
        CP16(sB + off + 128 * 80, b0 + 2 * b64);
        CP16(sB + off + 192 * 80, b0 + 3 * b64);
        CP_COMMIT();
    };

    issue(0, 0); issue(1, 1); issue(2, 2);

    const uint32_t aBase = smb + (wm * 64 + (lane & 15)) * 80 + (lane >> 4) * 16;
    const uint32_t bBase = smb + 10240 +
        (wn * 64 + (lane & 7) + ((lane >> 4) << 3)) * 80 + ((lane >> 3) & 1) * 16;

    #pragma unroll 1
    for (int c = 0; c < NCH; c++) {
        CP_WAIT2();
        __syncthreads();
        const uint32_t off = (c & 3) * STG_B;
        if (c + 3 < NCH) issue((c + 3) & 3, c + 3);
        else CP_COMMIT();                 // keep group count uniform
        #pragma unroll
        for (int ks = 0; ks < 2; ks++) {
            uint32_t af[4][4], bf[4][4];
            #pragma unroll
            for (int i = 0; i < 4; i++) ldsm4(af[i], aBase + off + i * 16 * 80 + ks * 32);
            #pragma unroll
            for (int p = 0; p < 4; p++) ldsm4(bf[p], bBase + off + p * 16 * 80 + ks * 32);
            #pragma unroll
            for (int i = 0; i < 4; i++)
                #pragma unroll
                for (int j = 0; j < 8; j++)
                    mma16816(acc[i][j], af[i], bf[j >> 1][(j & 1) * 2],
                             bf[j >> 1][(j & 1) * 2 + 1]);
        }
    }
}

// ---------------------------------------------------------------------------
// Kernel 1: LayerNorm over channels with transpose -> fp16 [side][p][c]
// ---------------------------------------------------------------------------
__global__ __launch_bounds__(256) void ln_kernel(const float* __restrict__ x,
                                                 const float* __restrict__ gm,
                                                 const float* __restrict__ bt,
                                                 int side) {
    int b  = blockIdx.y;
    int p0 = blockIdx.x << 5;
    int tid = threadIdx.x, lane = tid & 31, warp = tid >> 5;

    __shared__ float tile[CH][33];
    __shared__ float red[2][8][32];
    __shared__ float mu_s[32], rs_s[32];

    #pragma unroll 4
    for (int i = 0; i < 32; i++) {
        int c = (warp << 5) + i;
        tile[c][lane] = x[((size_t)b * CH + c) * HW + p0 + lane];
    }
    __syncthreads();

    {
        int pl = tid & 31, seg = tid >> 5;
        float s = 0.f, s2 = 0.f;
        #pragma unroll 8
        for (int c = seg * 32; c < seg * 32 + 32; c++) {
            float v = tile[c][pl];
            s += v; s2 += v * v;
        }
        red[0][seg][pl] = s;
        red[1][seg][pl] = s2;
    }
    __syncthreads();
    if (tid < 32) {
        float S = 0.f, S2 = 0.f;
        #pragma unroll
        for (int g = 0; g < 8; g++) { S += red[0][g][tid]; S2 += red[1][g][tid]; }
        float mu  = S * (1.f / 256.f);
        float var = S2 * (1.f / 256.f) - mu * mu;
        mu_s[tid] = mu;
        rs_s[tid] = rsqrtf(var + 1e-5f);
    }
    __syncthreads();

    __half* xh = g_xh + ((size_t)side << 22);
    #pragma unroll
    for (int pp = warp * 4; pp < warp * 4 + 4; pp++) {
        float mu = mu_s[pp], rs = rs_s[pp];
        #pragma unroll
        for (int c = lane; c < CH; c += 32) {
            float v = (tile[c][pp] - mu) * rs * gm[c] + bt[c];
            xh[((size_t)(b * HW + p0 + pp)) * 256 + c] = __float2half_rn(v);
        }
    }
}

// ---------------------------------------------------------------------------
// Kernel 2: weight transpose+convert: g_wh[n][k] = W[k][n], 4 matrices
// ---------------------------------------------------------------------------
__global__ __launch_bounds__(256) void wconv_kernel(const float* __restrict__ Wq,
                                                    const float* __restrict__ Wk,
                                                    const float* __restrict__ Wv,
                                                    const float* __restrict__ Wo) {
    int n = blockIdx.x, k = threadIdx.x;
    const float* W = (n < 256) ? Wq : (n < 512) ? Wk : (n < 768) ? Wv : Wo;
    g_wh[(size_t)n * 256 + k] = __float2half_rn(W[(size_t)k * 256 + (n & 255)]);
}

// ---------------------------------------------------------------------------
// Kernel 3: fused QKV GEMM. grid (3, 128, 2). CTA n0: 0=Q 256=K 512=V
// ---------------------------------------------------------------------------
__global__ __launch_bounds__(256, 1) void qkv_mma() {
    extern __shared__ char smraw[];
    const uint32_t smb = smem_u32(smraw);
    const int side = blockIdx.z;
    const int m0 = blockIdx.y << 7, n0 = blockIdx.x << 8;

    const __half* Ag = g_xh + ((size_t)side << 22) + (size_t)m0 * 256;
    const __half* Bg = g_wh + (size_t)n0 * 256;

    float acc[4][8][4] = {};
    gemm_core<8>(Ag, Bg, 256, 256, smb, acc);

    const int tid = threadIdx.x, wid = tid >> 5, lane = tid & 31;
    const int wm = wid >> 2, wn = wid & 3;
    const int qr = lane >> 2, qc = lane & 3;

    const int z  = side * 4 + (m0 >> 12);
    const int pb = m0 & 4095;

    if (n0 < 512) {
        __half* dst = (n0 == 0 ? g_qh : g_kh) + ((size_t)z << 20);
        #pragma unroll
        for (int i = 0; i < 4; i++) {
            int p = pb + wm * 64 + i * 16 + qr;
            #pragma unroll
            for (int j = 0; j < 8; j++) {
                int col = wn * 64 + j * 8 + qc * 2;
                *(__half2*)(dst + (size_t)p * 256 + col) =
                    __floats2half2_rn(acc[i][j][0], acc[i][j][1]);
                *(__half2*)(dst + (size_t)(p + 8) * 256 + col) =
                    __floats2half2_rn(acc[i][j][2], acc[i][j][3]);
            }
        }
    } else {
        // V: transpose via smem -> g_vth[z][c][m]
        __syncthreads();
        __half* st = (__half*)smraw;   // [256 c][136 m]
        #pragma unroll
        for (int i = 0; i < 4; i++) {
            int ml = wm * 64 + i * 16 + qr;
            #pragma unroll
            for (int j = 0; j < 8; j++) {
                int nl = wn * 64 + j * 8 + qc * 2;
                st[(size_t)nl * 136 + ml]           = __float2half_rn(acc[i][j][0]);
                st[(size_t)(nl + 1) * 136 + ml]     = __float2half_rn(acc[i][j][1]);
                st[(size_t)nl * 136 + ml + 8]       = __float2half_rn(acc[i][j][2]);
                st[(size_t)(nl + 1) * 136 + ml + 8] = __float2half_rn(acc[i][j][3]);
            }
        }
        __syncthreads();
        __half* dst = g_vth + ((size_t)z << 20) + pb;
        for (int idx = tid; idx < 256 * 16; idx += 256) {
            int r = idx >> 4, g = idx & 15;
            uint4 v = *(const uint4*)(st + (size_t)r * 136 + g * 8);
            *(uint4*)(dst + (size_t)r * 4096 + g * 8) = v;
        }
    }
}

// ---------------------------------------------------------------------------
// Kernel 4: scores  E[z,m,n] = exp(scale * Q[z][m] . K[z'][n]) -> fp16
// grid (16, 32, 8)
// ---------------------------------------------------------------------------
__global__ __launch_bounds__(256, 1) void scores_mma() {
    extern __shared__ char smraw[];
    const uint32_t smb = smem_u32(smraw);
    const int z = blockIdx.z;
    const int zk = ((z >> 2) ^ 1) * 4 + (z & 3);
    const int m0 = blockIdx.y << 7, n0 = blockIdx.x << 8;

    const __half* Ag = g_qh + ((size_t)z << 20) + (size_t)m0 * 256;
    const __half* Bg = g_kh + ((size_t)zk << 20) + (size_t)n0 * 256;

    float acc[4][8][4] = {};
    gemm_core<8>(Ag, Bg, 256, 256, smb, acc);

    const int tid = threadIdx.x, wid = tid >> 5, lane = tid & 31;
    const int wm = wid >> 2, wn = wid & 3;
    const int qr = lane >> 2, qc = lane & 3;

    __half* Ce = g_eh + ((size_t)z << 24);
    const float scale = 0.0625f;
    #pragma unroll
    for (int i = 0; i < 4; i++) {
        int m = m0 + wm * 64 + i * 16 + qr;
        #pragma unroll
        for (int j = 0; j < 8; j++) {
            int n = n0 + wn * 64 + j * 8 + qc * 2;
            *(__half2*)(Ce + (size_t)m * 4096 + n) =
                __floats2half2_rn(__expf(acc[i][j][0] * scale),
                                  __expf(acc[i][j][1] * scale));
            *(__half2*)(Ce + (size_t)(m + 8) * 4096 + n) =
                __floats2half2_rn(__expf(acc[i][j][2] * scale),
                                  __expf(acc[i][j][3] * scale));
        }
    }
}

// ---------------------------------------------------------------------------
// Kernel 5: P = E / sum_b E, in place on g_eh
// ---------------------------------------------------------------------------
__global__ __launch_bounds__(256) void pnorm_kernel() {
    size_t gid = (size_t)blockIdx.x * 256 + threadIdx.x;
    int side = (int)(gid >> 21);
    size_t nm = (gid & 0x1FFFFFull) << 3;
    __half* base = g_eh + (((size_t)side * 4) << 24) + nm;

    uint4 e[BATCH];
    #pragma unroll
    for (int b = 0; b < BATCH; b++) e[b] = *(const uint4*)(base + ((size_t)b << 24));

    #pragma unroll
    for (int t = 0; t < 4; t++) {
        uint32_t* w0 = &((uint32_t*)&e[0])[t];
        uint32_t* w1 = &((uint32_t*)&e[1])[t];
        uint32_t* w2 = &((uint32_t*)&e[2])[t];
        uint32_t* w3 = &((uint32_t*)&e[3])[t];
        float2 f0 = __half22float2(*(__half2*)w0);
        float2 f1 = __half22float2(*(__half2*)w1);
        float2 f2 = __half22float2(*(__half2*)w2);
        float2 f3 = __half22float2(*(__half2*)w3);
        float rx = 1.0f / (f0.x + f1.x + f2.x + f3.x);
        float ry = 1.0f / (f0.y + f1.y + f2.y + f3.y);
        *(__half2*)w0 = __floats2half2_rn(f0.x * rx, f0.y * ry);
        *(__half2*)w1 = __floats2half2_rn(f1.x * rx, f1.y * ry);
        *(__half2*)w2 = __floats2half2_rn(f2.x * rx, f2.y * ry);
        *(__half2*)w3 = __floats2half2_rn(f3.x * rx, f3.y * ry);
    }
    #pragma unroll
    for (int b = 0; b < BATCH; b++) *(uint4*)(base + ((size_t)b << 24)) = e[b];
}

// ---------------------------------------------------------------------------
// Kernel 6: O[z] = P[z] @ V[z] -> fp16.  grid (1, 32, 8), K = 4096
// ---------------------------------------------------------------------------
__global__ __launch_bounds__(256, 1) void pv_mma() {
    extern __shared__ char smraw[];
    const uint32_t smb = smem_u32(smraw);
    const int z = blockIdx.z;
    const int m0 = blockIdx.y << 7;

    const __half* Ag = g_eh  + ((size_t)z << 24) + (size_t)m0 * 4096;
    const __half* Bg = g_vth + ((size_t)z << 20);

    float acc[4][8][4] = {};
    gemm_core<128>(Ag, Bg, 4096, 4096, smb, acc);

    const int tid = threadIdx.x, wid = tid >> 5, lane = tid & 31;
    const int wm = wid >> 2, wn = wid & 3;
    const int qr = lane >> 2, qc = lane & 3;

    __half* Co = g_oh + ((size_t)z << 20);
    #pragma unroll
    for (int i = 0; i < 4; i++) {
        int m = m0 + wm * 64 + i * 16 + qr;
        #pragma unroll
        for (int j = 0; j < 8; j++) {
            int n = wn * 64 + j * 8 + qc * 2;
            *(__half2*)(Co + (size_t)m * 256 + n) =
                __floats2half2_rn(acc[i][j][0], acc[i][j][1]);
            *(__half2*)(Co + (size_t)(m + 8) * 256 + n) =
                __floats2half2_rn(acc[i][j][2], acc[i][j][3]);
        }
    }
}

// ---------------------------------------------------------------------------
// Kernel 7: out[b,c,p] = x[b,c,p] + (O @ Wo)[b,p,c]   (fp16 MMA + transpose)
// grid (1, 128, 2)
// ---------------------------------------------------------------------------
__global__ __launch_bounds__(256, 1) void out_mma(const float* __restrict__ xl,
                                                  const float* __restrict__ xr,
                                                  float* __restrict__ outp) {
    extern __shared__ char smraw[];
    const uint32_t smb = smem_u32(smraw);
    const int side = blockIdx.z;
    const int m0 = blockIdx.y << 7;

    const __half* Ag = g_oh + ((size_t)side << 22) + (size_t)m0 * 256;
    const __half* Bg = g_wh + (size_t)768 * 256;

    float acc[4][8][4] = {};
    gemm_core<8>(Ag, Bg, 256, 256, smb, acc);

    const int tid = threadIdx.x, wid = tid >> 5, lane = tid & 31;
    const int wm = wid >> 2, wn = wid & 3;
    const int qr = lane >> 2, qc = lane & 3;

    __syncthreads();
    __half* st = (__half*)smraw;   // [128 m][258 n pitch]
    #pragma unroll
    for (int i = 0; i < 4; i++) {
        int ml = wm * 64 + i * 16 + qr;
        #pragma unroll
        for (int j = 0; j < 8; j++) {
            int nl = wn * 64 + j * 8 + qc * 2;
            *(__half2*)(st + (size_t)ml * 258 + nl) =
                __floats2half2_rn(acc[i][j][0], acc[i][j][1]);
            *(__half2*)(st + (size_t)(ml + 8) * 258 + nl) =
                __floats2half2_rn(acc[i][j][2], acc[i][j][3]);
        }
    }
    __syncthreads();

    const float* x = side ? xr : xl;
    float* op = outp + ((size_t)side << 22);
    const int b = m0 >> 12, p0 = m0 & 4095;
    for (int idx = tid; idx < 128 * 256; idx += 256) {
        int cl = idx >> 7, pl = idx & 127;
        size_t off = ((size_t)b * 256 + cl) * 4096 + p0 + pl;
        op[off] = x[off] + __half2float(st[(size_t)pl * 258 + cl]);
    }
}

// ---------------------------------------------------------------------------
extern "C" void kernel_launch(void* const* d_in, const int* in_sizes, int n_in,
                              void* d_out, int out_size) {
    const float* x_l = (const float*)d_in[0];
    const float* x_r = (const float*)d_in[1];
    const float* Wq  = (const float*)d_in[2];
    const float* Wk  = (const float*)d_in[3];
    const float* Wv  = (const float*)d_in[4];
    const float* Wo  = (const float*)d_in[5];
    const float* g1  = (const float*)d_in[6];
    const float* b1  = (const float*)d_in[7];
    const float* g2  = (const float*)d_in[8];
    const float* b2  = (const float*)d_in[9];
    float* out = (float*)d_out;

    cudaFuncSetAttribute(qkv_mma,    cudaFuncAttributeMaxDynamicSharedMemorySize, SMEM_MMA);
    cudaFuncSetAttribute(scores_mma, cudaFuncAttributeMaxDynamicSharedMemorySize, SMEM_MMA);
    cudaFuncSetAttribute(pv_mma,     cudaFuncAttributeMaxDynamicSharedMemorySize, SMEM_MMA);
    cudaFuncSetAttribute(out_mma,    cudaFuncAttributeMaxDynamicSharedMemorySize, SMEM_MMA);

    // 1) LayerNorm -> fp16 [p][c], weights -> fp16 [n][k]
    ln_kernel<<<dim3(HW / 32, BATCH), 256>>>(x_l, g1, b1, 0);
    ln_kernel<<<dim3(HW / 32, BATCH), 256>>>(x_r, g2, b2, 1);
    wconv_kernel<<<1024, 256>>>(Wq, Wk, Wv, Wo);

    // 2) fused QKV (V transposed)
    qkv_mma<<<dim3(3, 128, 2), 256, SMEM_MMA>>>();

    // 3) E = exp(scale * Q @ K^T)
    scores_mma<<<dim3(16, 32, 8), 256, SMEM_MMA>>>();

    // 4) P = E / sum_b E (in place)
    pnorm_kernel<<<16384, 256>>>();

    // 5) O = P @ V -> fp16
    pv_mma<<<dim3(1, 32, 8), 256, SMEM_MMA>>>();

    // 6) out = x + (O @ Wo)^T
    out_mma<<<dim3(1, 128, 2), 256, SMEM_MMA>>>(x_l, x_r, out);
}

// round 6
// speedup vs baseline: 1.0791x; 1.0791x over previous
#include <cuda_runtime.h>
#include <cuda_fp16.h>
#include <cstdint>

#define HW    4096
#define CH    256
#define BATCH 4

// fp16 operands / activations
__device__ __half g_xh [2ull * BATCH * HW * CH];          // LN output [side][p][c]
__device__ __half g_wh [1024ull * 256];                   // [Wq|Wk|Wv|Wo]^T: [n][k]
__device__ __half g_qh [2ull * BATCH * HW * CH];          // [z][p][c]
__device__ __half g_kh [2ull * BATCH * HW * CH];          // [z][p][c]
__device__ __half g_vth[2ull * BATCH * HW * CH];          // V^T: [z][c][m]
__device__ __half g_eh [2ull * BATCH * HW * HW];          // E then P (in place)
__device__ __half g_oh [2ull * BATCH * HW * CH];          // PV output fp16 [side][p][c]

// ---------------------------------------------------------------------------
// low-level helpers
// ---------------------------------------------------------------------------
__device__ __forceinline__ uint32_t smem_u32(const void* p) {
    uint32_t a;
    asm("{ .reg .u64 t; cvta.to.shared.u64 t, %1; cvt.u32.u64 %0, t; }"
        : "=r"(a) : "l"(p));
    return a;
}

__device__ __forceinline__ void mma16816(float (&c)[4], const uint32_t (&a)[4],
                                         uint32_t b0, uint32_t b1) {
    asm volatile(
        "mma.sync.aligned.m16n8k16.row.col.f32.f16.f16.f32 "
        "{%0,%1,%2,%3}, {%4,%5,%6,%7}, {%8,%9}, {%0,%1,%2,%3};"
        : "+f"(c[0]), "+f"(c[1]), "+f"(c[2]), "+f"(c[3])
        : "r"(a[0]), "r"(a[1]), "r"(a[2]), "r"(a[3]), "r"(b0), "r"(b1));
}

__device__ __forceinline__ void ldsm4(uint32_t (&r)[4], uint32_t addr) {
    asm volatile("ldmatrix.sync.aligned.m8n8.x4.shared.b16 {%0,%1,%2,%3}, [%4];"
        : "=r"(r[0]), "=r"(r[1]), "=r"(r[2]), "=r"(r[3]) : "r"(addr));
}

#define CP16(s, g) \
    asm volatile("cp.async.cg.shared.global [%0], [%1], 16;" :: "r"(s), "l"(g))
#define CP_COMMIT() asm volatile("cp.async.commit_group;")
#define CP_WAIT3()  asm volatile("cp.async.wait_group 3;")

// ---------------------------------------------------------------------------
// GEMM core: CTA 128x128, k-chunk 32 halfs, 5-stage cp.async pipeline,
// ldmatrix fragments. 256 threads = 8 warps (2m x 4n), warp tile 64x32.
// smem stage: A 128 rows x 80B + B 128 x 80B = 20480 B; 5 stages = 100 KB.
// 2 CTAs/SM.
// ---------------------------------------------------------------------------
#define STG_B    20480
#define SMEM_MMA 102400

template <int NCH>
__device__ __forceinline__ void gemm_core(const __half* __restrict__ Ag,
                                          const __half* __restrict__ Bg,
                                          int ldA, int ldB, uint32_t smb,
                                          float (&acc)[4][4][4]) {
    const int tid  = threadIdx.x;
    const int lane = tid & 31, wid = tid >> 5;
    const int wm = wid >> 2, wn = wid & 3;

    const int lr = tid >> 2;                 // load row 0..63
    const __half* agp = Ag + (size_t)lr * ldA + (tid & 3) * 8;
    const __half* bgp = Bg + (size_t)lr * ldB + (tid & 3) * 8;
    const size_t a64 = (size_t)64 * ldA, b64 = (size_t)64 * ldB;

    const uint32_t sA = smb + lr * 80 + (tid & 3) * 16;
    const uint32_t sB = sA + 10240;

    auto issue = [&](int s, int c) {
        const uint32_t off = s * STG_B;
        const __half* a0 = agp + (size_t)c * 32;
        const __half* b0 = bgp + (size_t)c * 32;
        CP16(sA + off,           a0);
        CP16(sA + off + 64 * 80, a0 + a64);
        CP16(sB + off,           b0);
        CP16(sB + off + 64 * 80, b0 + b64);
        CP_COMMIT();
    };

    issue(0, 0); issue(1, 1); issue(2, 2); issue(3, 3);

    const uint32_t aBase = smb + (wm * 64 + (lane & 15)) * 80 + (lane >> 4) * 16;
    const uint32_t bBase = smb + 10240 +
        (wn * 32 + (lane & 7) + ((lane >> 4) << 3)) * 80 + ((lane >> 3) & 1) * 16;

    int stg = 0;                 // stage of chunk c (mod 5)
    int nxt = 4;                 // stage for chunk c+4
    #pragma unroll 1
    for (int c = 0; c < NCH; c++) {
        CP_WAIT3();
        __syncthreads();
        const uint32_t off = stg * STG_B;
        if (c + 4 < NCH) issue(nxt, c + 4);
        else CP_COMMIT();                 // keep group count uniform
        if (++stg == 5) stg = 0;
        if (++nxt == 5) nxt = 0;
        #pragma unroll
        for (int ks = 0; ks < 2; ks++) {
            uint32_t af[4][4], bf[2][4];
            #pragma unroll
            for (int i = 0; i < 4; i++) ldsm4(af[i], aBase + off + i * 16 * 80 + ks * 32);
            #pragma unroll
            for (int p = 0; p < 2; p++) ldsm4(bf[p], bBase + off + p * 16 * 80 + ks * 32);
            #pragma unroll
            for (int i = 0; i < 4; i++)
                #pragma unroll
                for (int j = 0; j < 4; j++)
                    mma16816(acc[i][j], af[i], bf[j >> 1][(j & 1) * 2],
                             bf[j >> 1][(j & 1) * 2 + 1]);
        }
    }
}

// ---------------------------------------------------------------------------
// Kernel 1: LayerNorm over channels with transpose -> fp16 [side][p][c]
// ---------------------------------------------------------------------------
__global__ __launch_bounds__(256) void ln_kernel(const float* __restrict__ x,
                                                 const float* __restrict__ gm,
                                                 const float* __restrict__ bt,
                                                 int side) {
    int b  = blockIdx.y;
    int p0 = blockIdx.x << 5;
    int tid = threadIdx.x, lane = tid & 31, warp = tid >> 5;

    __shared__ float tile[CH][33];
    __shared__ float red[2][8][32];
    __shared__ float mu_s[32], rs_s[32];

    #pragma unroll 4
    for (int i = 0; i < 32; i++) {
        int c = (warp << 5) + i;
        tile[c][lane] = x[((size_t)b * CH + c) * HW + p0 + lane];
    }
    __syncthreads();

    {
        int pl = tid & 31, seg = tid >> 5;
        float s = 0.f, s2 = 0.f;
        #pragma unroll 8
        for (int c = seg * 32; c < seg * 32 + 32; c++) {
            float v = tile[c][pl];
            s += v; s2 += v * v;
        }
        red[0][seg][pl] = s;
        red[1][seg][pl] = s2;
    }
    __syncthreads();
    if (tid < 32) {
        float S = 0.f, S2 = 0.f;
        #pragma unroll
        for (int g = 0; g < 8; g++) { S += red[0][g][tid]; S2 += red[1][g][tid]; }
        float mu  = S * (1.f / 256.f);
        float var = S2 * (1.f / 256.f) - mu * mu;
        mu_s[tid] = mu;
        rs_s[tid] = rsqrtf(var + 1e-5f);
    }
    __syncthreads();

    __half* xh = g_xh + ((size_t)side << 22);
    #pragma unroll
    for (int pp = warp * 4; pp < warp * 4 + 4; pp++) {
        float mu = mu_s[pp], rs = rs_s[pp];
        #pragma unroll
        for (int c = lane; c < CH; c += 32) {
            float v = (tile[c][pp] - mu) * rs * gm[c] + bt[c];
            xh[((size_t)(b * HW + p0 + pp)) * 256 + c] = __float2half_rn(v);
        }
    }
}

// ---------------------------------------------------------------------------
// Kernel 2: weight transpose+convert: g_wh[n][k] = W[k][n], 4 matrices
// ---------------------------------------------------------------------------
__global__ __launch_bounds__(256) void wconv_kernel(const float* __restrict__ Wq,
                                                    const float* __restrict__ Wk,
                                                    const float* __restrict__ Wv,
                                                    const float* __restrict__ Wo) {
    int n = blockIdx.x, k = threadIdx.x;
    const float* W = (n < 256) ? Wq : (n < 512) ? Wk : (n < 768) ? Wv : Wo;
    g_wh[(size_t)n * 256 + k] = __float2half_rn(W[(size_t)k * 256 + (n & 255)]);
}

// ---------------------------------------------------------------------------
// Kernel 3: fused QKV GEMM. grid (6, 128, 2). N: [0,256)Q [256,512)K [512,768)V
// ---------------------------------------------------------------------------
__global__ __launch_bounds__(256, 2) void qkv_mma() {
    extern __shared__ char smraw[];
    const uint32_t smb = smem_u32(smraw);
    const int side = blockIdx.z;
    const int m0 = blockIdx.y << 7, n0 = blockIdx.x << 7;

    const __half* Ag = g_xh + ((size_t)side << 22) + (size_t)m0 * 256;
    const __half* Bg = g_wh + (size_t)n0 * 256;

    float acc[4][4][4] = {};
    gemm_core<8>(Ag, Bg, 256, 256, smb, acc);

    const int tid = threadIdx.x, wid = tid >> 5, lane = tid & 31;
    const int wm = wid >> 2, wn = wid & 3;
    const int qr = lane >> 2, qc = lane & 3;

    const int z  = side * 4 + (m0 >> 12);
    const int pb = m0 & 4095;

    if (n0 < 512) {
        __half* dst = ((n0 >> 8) == 0 ? g_qh : g_kh) + ((size_t)z << 20);
        const int nloc = n0 & 255;
        #pragma unroll
        for (int i = 0; i < 4; i++) {
            int p = pb + wm * 64 + i * 16 + qr;
            #pragma unroll
            for (int j = 0; j < 4; j++) {
                int col = nloc + wn * 32 + j * 8 + qc * 2;
                *(__half2*)(dst + (size_t)p * 256 + col) =
                    __floats2half2_rn(acc[i][j][0], acc[i][j][1]);
                *(__half2*)(dst + (size_t)(p + 8) * 256 + col) =
                    __floats2half2_rn(acc[i][j][2], acc[i][j][3]);
            }
        }
    } else {
        // V: transpose via smem -> g_vth[z][c][m]
        __syncthreads();
        __half* st = (__half*)smraw;   // [128 n][136 m]
        #pragma unroll
        for (int i = 0; i < 4; i++) {
            int ml = wm * 64 + i * 16 + qr;
            #pragma unroll
            for (int j = 0; j < 4; j++) {
                int nl = wn * 32 + j * 8 + qc * 2;
                st[(size_t)nl * 136 + ml]           = __float2half_rn(acc[i][j][0]);
                st[(size_t)(nl + 1) * 136 + ml]     = __float2half_rn(acc[i][j][1]);
                st[(size_t)nl * 136 + ml + 8]       = __float2half_rn(acc[i][j][2]);
                st[(size_t)(nl + 1) * 136 + ml + 8] = __float2half_rn(acc[i][j][3]);
            }
        }
        __syncthreads();
        const int cv0 = n0 - 512;
        __half* dst = g_vth + ((size_t)z << 20) + pb;
        for (int idx = tid; idx < 128 * 16; idx += 256) {
            int r = idx >> 4, g = idx & 15;
            uint4 v = *(const uint4*)(st + (size_t)r * 136 + g * 8);
            *(uint4*)(dst + (size_t)(cv0 + r) * 4096 + g * 8) = v;
        }
    }
}

// ---------------------------------------------------------------------------
// Kernel 4: scores  E[z,m,n] = exp(scale * Q[z][m] . K[z'][n]) -> fp16
// grid (32, 32, 8)
// ---------------------------------------------------------------------------
__global__ __launch_bounds__(256, 2) void scores_mma() {
    extern __shared__ char smraw[];
    const uint32_t smb = smem_u32(smraw);
    const int z = blockIdx.z;
    const int zk = ((z >> 2) ^ 1) * 4 + (z & 3);
    const int m0 = blockIdx.y << 7, n0 = blockIdx.x << 7;

    const __half* Ag = g_qh + ((size_t)z << 20) + (size_t)m0 * 256;
    const __half* Bg = g_kh + ((size_t)zk << 20) + (size_t)n0 * 256;

    float acc[4][4][4] = {};
    gemm_core<8>(Ag, Bg, 256, 256, smb, acc);

    const int tid = threadIdx.x, wid = tid >> 5, lane = tid & 31;
    const int wm = wid >> 2, wn = wid & 3;
    const int qr = lane >> 2, qc = lane & 3;

    __half* Ce = g_eh + ((size_t)z << 24);
    const float scale = 0.0625f;
    #pragma unroll
    for (int i = 0; i < 4; i++) {
        int m = m0 + wm * 64 + i * 16 + qr;
        #pragma unroll
        for (int j = 0; j < 4; j++) {
            int n = n0 + wn * 32 + j * 8 + qc * 2;
            *(__half2*)(Ce + (size_t)m * 4096 + n) =
                __floats2half2_rn(__expf(acc[i][j][0] * scale),
                                  __expf(acc[i][j][1] * scale));
            *(__half2*)(Ce + (size_t)(m + 8) * 4096 + n) =
                __floats2half2_rn(__expf(acc[i][j][2] * scale),
                                  __expf(acc[i][j][3] * scale));
        }
    }
}

// ---------------------------------------------------------------------------
// Kernel 5: P = E / sum_b E, in place on g_eh
// ---------------------------------------------------------------------------
__global__ __launch_bounds__(256) void pnorm_kernel() {
    size_t gid = (size_t)blockIdx.x * 256 + threadIdx.x;
    int side = (int)(gid >> 21);
    size_t nm = (gid & 0x1FFFFFull) << 3;
    __half* base = g_eh + (((size_t)side * 4) << 24) + nm;

    uint4 e[BATCH];
    #pragma unroll
    for (int b = 0; b < BATCH; b++) e[b] = *(const uint4*)(base + ((size_t)b << 24));

    #pragma unroll
    for (int t = 0; t < 4; t++) {
        uint32_t* w0 = &((uint32_t*)&e[0])[t];
        uint32_t* w1 = &((uint32_t*)&e[1])[t];
        uint32_t* w2 = &((uint32_t*)&e[2])[t];
        uint32_t* w3 = &((uint32_t*)&e[3])[t];
        float2 f0 = __half22float2(*(__half2*)w0);
        float2 f1 = __half22float2(*(__half2*)w1);
        float2 f2 = __half22float2(*(__half2*)w2);
        float2 f3 = __half22float2(*(__half2*)w3);
        float rx = 1.0f / (f0.x + f1.x + f2.x + f3.x);
        float ry = 1.0f / (f0.y + f1.y + f2.y + f3.y);
        *(__half2*)w0 = __floats2half2_rn(f0.x * rx, f0.y * ry);
        *(__half2*)w1 = __floats2half2_rn(f1.x * rx, f1.y * ry);
        *(__half2*)w2 = __floats2half2_rn(f2.x * rx, f2.y * ry);
        *(__half2*)w3 = __floats2half2_rn(f3.x * rx, f3.y * ry);
    }
    #pragma unroll
    for (int b = 0; b < BATCH; b++) *(uint4*)(base + ((size_t)b << 24)) = e[b];
}

// ---------------------------------------------------------------------------
// Kernel 6: O[z] = P[z] @ V[z] -> fp16.  grid (2, 32, 8), K = 4096
// ---------------------------------------------------------------------------
__global__ __launch_bounds__(256, 2) void pv_mma() {
    extern __shared__ char smraw[];
    const uint32_t smb = smem_u32(smraw);
    const int z = blockIdx.z;
    const int m0 = blockIdx.y << 7, n0 = blockIdx.x << 7;

    const __half* Ag = g_eh  + ((size_t)z << 24) + (size_t)m0 * 4096;
    const __half* Bg = g_vth + ((size_t)z << 20) + (size_t)n0 * 4096;

    float acc[4][4][4] = {};
    gemm_core<128>(Ag, Bg, 4096, 4096, smb, acc);

    const int tid = threadIdx.x, wid = tid >> 5, lane = tid & 31;
    const int wm = wid >> 2, wn = wid & 3;
    const int qr = lane >> 2, qc = lane & 3;

    __half* Co = g_oh + ((size_t)z << 20);
    #pragma unroll
    for (int i = 0; i < 4; i++) {
        int m = m0 + wm * 64 + i * 16 + qr;
        #pragma unroll
        for (int j = 0; j < 4; j++) {
            int n = n0 + wn * 32 + j * 8 + qc * 2;
            *(__half2*)(Co + (size_t)m * 256 + n) =
                __floats2half2_rn(acc[i][j][0], acc[i][j][1]);
            *(__half2*)(Co + (size_t)(m + 8) * 256 + n) =
                __floats2half2_rn(acc[i][j][2], acc[i][j][3]);
        }
    }
}

// ---------------------------------------------------------------------------
// Kernel 7: out[b,c,p] = x[b,c,p] + (O @ Wo)[b,p,c]   (fp16 MMA + transpose)
// grid (2, 128, 2)
// ---------------------------------------------------------------------------
__global__ __launch_bounds__(256, 2) void out_mma(const float* __restrict__ xl,
                                                  const float* __restrict__ xr,
                                                  float* __restrict__ outp) {
    extern __shared__ char smraw[];
    const uint32_t smb = smem_u32(smraw);
    const int side = blockIdx.z;
    const int m0 = blockIdx.y << 7, n0 = blockIdx.x << 7;

    const __half* Ag = g_oh + ((size_t)side << 22) + (size_t)m0 * 256;
    const __half* Bg = g_wh + (size_t)(768 + n0) * 256;

    float acc[4][4][4] = {};
    gemm_core<8>(Ag, Bg, 256, 256, smb, acc);

    const int tid = threadIdx.x, wid = tid >> 5, lane = tid & 31;
    const int wm = wid >> 2, wn = wid & 3;
    const int qr = lane >> 2, qc = lane & 3;

    __syncthreads();
    float* st = (float*)smraw;   // [128 m][129]
    #pragma unroll
    for (int i = 0; i < 4; i++) {
        int ml = wm * 64 + i * 16 + qr;
        #pragma unroll
        for (int j = 0; j < 4; j++) {
            int nl = wn * 32 + j * 8 + qc * 2;
            st[(size_t)ml * 129 + nl]           = acc[i][j][0];
            st[(size_t)ml * 129 + nl + 1]       = acc[i][j][1];
            st[(size_t)(ml + 8) * 129 + nl]     = acc[i][j][2];
            st[(size_t)(ml + 8) * 129 + nl + 1] = acc[i][j][3];
        }
    }
    __syncthreads();

    const float* x = side ? xr : xl;
    float* op = outp + ((size_t)side << 22);
    const int b = m0 >> 12, p0 = m0 & 4095;
    for (int idx = tid; idx < 128 * 128; idx += 256) {
        int cl = idx >> 7, pl = idx & 127;
        size_t off = ((size_t)b * 256 + n0 + cl) * 4096 + p0 + pl;
        op[off] = x[off] + st[(size_t)pl * 129 + cl];
    }
}

// ---------------------------------------------------------------------------
extern "C" void kernel_launch(void* const* d_in, const int* in_sizes, int n_in,
                              void* d_out, int out_size) {
    const float* x_l = (const float*)d_in[0];
    const float* x_r = (const float*)d_in[1];
    const float* Wq  = (const float*)d_in[2];
    const float* Wk  = (const float*)d_in[3];
    const float* Wv  = (const float*)d_in[4];
    const float* Wo  = (const float*)d_in[5];
    const float* g1  = (const float*)d_in[6];
    const float* b1  = (const float*)d_in[7];
    const float* g2  = (const float*)d_in[8];
    const float* b2  = (const float*)d_in[9];
    float* out = (float*)d_out;

    cudaFuncSetAttribute(qkv_mma,    cudaFuncAttributeMaxDynamicSharedMemorySize, SMEM_MMA);
    cudaFuncSetAttribute(scores_mma, cudaFuncAttributeMaxDynamicSharedMemorySize, SMEM_MMA);
    cudaFuncSetAttribute(pv_mma,     cudaFuncAttributeMaxDynamicSharedMemorySize, SMEM_MMA);
    cudaFuncSetAttribute(out_mma,    cudaFuncAttributeMaxDynamicSharedMemorySize, SMEM_MMA);

    // 1) LayerNorm -> fp16 [p][c], weights -> fp16 [n][k]
    ln_kernel<<<dim3(HW / 32, BATCH), 256>>>(x_l, g1, b1, 0);
    ln_kernel<<<dim3(HW / 32, BATCH), 256>>>(x_r, g2, b2, 1);
    wconv_kernel<<<1024, 256>>>(Wq, Wk, Wv, Wo);

    // 2) fused QKV (V transposed)
    qkv_mma<<<dim3(6, 128, 2), 256, SMEM_MMA>>>();

    // 3) E = exp(scale * Q @ K^T)
    scores_mma<<<dim3(32, 32, 8), 256, SMEM_MMA>>>();

    // 4) P = E / sum_b E (in place)
    pnorm_kernel<<<16384, 256>>>();

    // 5) O = P @ V -> fp16
    pv_mma<<<dim3(2, 32, 8), 256, SMEM_MMA>>>();

    // 6) out = x + (O @ Wo)^T
    out_mma<<<dim3(2, 128, 2), 256, SMEM_MMA>>>(x_l, x_r, out);
}

// round 7
// speedup vs baseline: 1.2170x; 1.1277x over previous
#include <cuda_runtime.h>
#include <cuda_fp16.h>
#include <cstdint>

#define HW    4096
#define CH    256
#define BATCH 4

// fp16 operands / activations
__device__ __half g_xh [2ull * BATCH * HW * CH];          // LN output [side][p][c]
__device__ __half g_wh [1024ull * 256];                   // [Wq|Wk|Wv|Wo]^T: [n][k]
__device__ __half g_qh [2ull * BATCH * HW * CH];          // [z][p][c]
__device__ __half g_kh [2ull * BATCH * HW * CH];          // [z][p][c]
__device__ __half g_vth[2ull * BATCH * HW * CH];          // V^T: [z][c][m]
__device__ __half g_eh [2ull * BATCH * HW * HW];          // E then P (in place)
__device__ __half g_oh [2ull * BATCH * HW * CH];          // PV output fp16 [side][p][c]

// ---------------------------------------------------------------------------
// low-level helpers
// ---------------------------------------------------------------------------
__device__ __forceinline__ uint32_t smem_u32(const void* p) {
    uint32_t a;
    asm("{ .reg .u64 t; cvta.to.shared.u64 t, %1; cvt.u32.u64 %0, t; }"
        : "=r"(a) : "l"(p));
    return a;
}

__device__ __forceinline__ void mma16816(float (&c)[4], const uint32_t (&a)[4],
                                         uint32_t b0, uint32_t b1) {
    asm volatile(
        "mma.sync.aligned.m16n8k16.row.col.f32.f16.f16.f32 "
        "{%0,%1,%2,%3}, {%4,%5,%6,%7}, {%8,%9}, {%0,%1,%2,%3};"
        : "+f"(c[0]), "+f"(c[1]), "+f"(c[2]), "+f"(c[3])
        : "r"(a[0]), "r"(a[1]), "r"(a[2]), "r"(a[3]), "r"(b0), "r"(b1));
}

__device__ __forceinline__ void ldsm4(uint32_t (&r)[4], uint32_t addr) {
    asm volatile("ldmatrix.sync.aligned.m8n8.x4.shared.b16 {%0,%1,%2,%3}, [%4];"
        : "=r"(r[0]), "=r"(r[1]), "=r"(r[2]), "=r"(r[3]) : "r"(addr));
}

#define CP16(s, g) \
    asm volatile("cp.async.cg.shared.global [%0], [%1], 16;" :: "r"(s), "l"(g))
#define CP_COMMIT() asm volatile("cp.async.commit_group;")
#define CP_WAIT1()  asm volatile("cp.async.wait_group 1;")

// ---------------------------------------------------------------------------
// GEMM core: CTA 128x128, k-chunk 64 halfs, 3-stage cp.async pipeline,
// ldmatrix fragments. 256 threads = 8 warps (2m x 4n), warp tile 64x32.
// smem stage: (128 A rows + 128 B rows) x 144B = 36864 B; 3 stages = 108 KB.
// 2 CTAs/SM. One wait+sync per 64 k-steps; warp-staggered ks order.
// ---------------------------------------------------------------------------
#define STG_B    36864
#define SMEM_MMA 110592

template <int NCH>   // number of k32 chunks; must be even
__device__ __forceinline__ void gemm_core(const __half* __restrict__ Ag,
                                          const __half* __restrict__ Bg,
                                          int ldA, int ldB, uint32_t smb,
                                          float (&acc)[4][4][4]) {
    const int tid  = threadIdx.x;
    const int lane = tid & 31, wid = tid >> 5;
    const int wm = wid >> 2, wn = wid & 3;

    const int lr = tid >> 3;                 // load row 0..31
    const int lc = tid & 7;                  // 16B column 0..7
    const __half* agp = Ag + (size_t)lr * ldA + lc * 8;
    const __half* bgp = Bg + (size_t)lr * ldB + lc * 8;

    const uint32_t sA = smb + lr * 144 + lc * 16;
    const uint32_t sB = sA + 128 * 144;

    auto issue = [&](int s, int c64) {
        const uint32_t off = s * STG_B;
        const __half* a0 = agp + (size_t)c64 * 64;
        const __half* b0 = bgp + (size_t)c64 * 64;
        #pragma unroll
        for (int r = 0; r < 4; r++) {
            CP16(sA + off + r * 32 * 144, a0 + (size_t)(r * 32) * ldA);
            CP16(sB + off + r * 32 * 144, b0 + (size_t)(r * 32) * ldB);
        }
        CP_COMMIT();
    };

    issue(0, 0); issue(1, 1);

    const uint32_t aBase = smb + (wm * 64 + (lane & 15)) * 144 + (lane >> 4) * 16;
    const uint32_t bBase = smb + 128 * 144 +
        (wn * 32 + (lane & 7) + ((lane >> 4) << 3)) * 144 + ((lane >> 3) & 1) * 16;

    const int NC64 = NCH / 2;
    int stg = 0, nxt = 2;
    #pragma unroll 1
    for (int c = 0; c < NC64; c++) {
        CP_WAIT1();
        __syncthreads();
        const uint32_t off = stg * STG_B;
        if (c + 2 < NC64) issue(nxt, c + 2);
        else CP_COMMIT();                 // keep group count uniform
        if (++stg == 3) stg = 0;
        if (++nxt == 3) nxt = 0;
        #pragma unroll
        for (int k4 = 0; k4 < 4; k4++) {
            const int ks = (k4 + 2 * wm) & 3;   // stagger m-groups
            uint32_t af[4][4], bf[2][4];
            #pragma unroll
            for (int i = 0; i < 4; i++) ldsm4(af[i], aBase + off + i * 16 * 144 + ks * 32);
            #pragma unroll
            for (int p = 0; p < 2; p++) ldsm4(bf[p], bBase + off + p * 16 * 144 + ks * 32);
            #pragma unroll
            for (int i = 0; i < 4; i++)
                #pragma unroll
                for (int j = 0; j < 4; j++)
                    mma16816(acc[i][j], af[i], bf[j >> 1][(j & 1) * 2],
                             bf[j >> 1][(j & 1) * 2 + 1]);
        }
    }
}

// ---------------------------------------------------------------------------
// Kernel 1: LayerNorm over channels with transpose -> fp16 [side][p][c]
// ---------------------------------------------------------------------------
__global__ __launch_bounds__(256) void ln_kernel(const float* __restrict__ x,
                                                 const float* __restrict__ gm,
                                                 const float* __restrict__ bt,
                                                 int side) {
    int b  = blockIdx.y;
    int p0 = blockIdx.x << 5;
    int tid = threadIdx.x, lane = tid & 31, warp = tid >> 5;

    __shared__ float tile[CH][33];
    __shared__ float red[2][8][32];
    __shared__ float mu_s[32], rs_s[32];

    #pragma unroll 4
    for (int i = 0; i < 32; i++) {
        int c = (warp << 5) + i;
        tile[c][lane] = x[((size_t)b * CH + c) * HW + p0 + lane];
    }
    __syncthreads();

    {
        int pl = tid & 31, seg = tid >> 5;
        float s = 0.f, s2 = 0.f;
        #pragma unroll 8
        for (int c = seg * 32; c < seg * 32 + 32; c++) {
            float v = tile[c][pl];
            s += v; s2 += v * v;
        }
        red[0][seg][pl] = s;
        red[1][seg][pl] = s2;
    }
    __syncthreads();
    if (tid < 32) {
        float S = 0.f, S2 = 0.f;
        #pragma unroll
        for (int g = 0; g < 8; g++) { S += red[0][g][tid]; S2 += red[1][g][tid]; }
        float mu  = S * (1.f / 256.f);
        float var = S2 * (1.f / 256.f) - mu * mu;
        mu_s[tid] = mu;
        rs_s[tid] = rsqrtf(var + 1e-5f);
    }
    __syncthreads();

    __half* xh = g_xh + ((size_t)side << 22);
    #pragma unroll
    for (int pp = warp * 4; pp < warp * 4 + 4; pp++) {
        float mu = mu_s[pp], rs = rs_s[pp];
        #pragma unroll
        for (int c = lane; c < CH; c += 32) {
            float v = (tile[c][pp] - mu) * rs * gm[c] + bt[c];
            xh[((size_t)(b * HW + p0 + pp)) * 256 + c] = __float2half_rn(v);
        }
    }
}

// ---------------------------------------------------------------------------
// Kernel 2: weight transpose+convert: g_wh[n][k] = W[k][n], 4 matrices
// ---------------------------------------------------------------------------
__global__ __launch_bounds__(256) void wconv_kernel(const float* __restrict__ Wq,
                                                    const float* __restrict__ Wk,
                                                    const float* __restrict__ Wv,
                                                    const float* __restrict__ Wo) {
    int n = blockIdx.x, k = threadIdx.x;
    const float* W = (n < 256) ? Wq : (n < 512) ? Wk : (n < 768) ? Wv : Wo;
    g_wh[(size_t)n * 256 + k] = __float2half_rn(W[(size_t)k * 256 + (n & 255)]);
}

// ---------------------------------------------------------------------------
// Kernel 3: fused QKV GEMM. grid (6, 128, 2). N: [0,256)Q [256,512)K [512,768)V
// ---------------------------------------------------------------------------
__global__ __launch_bounds__(256, 2) void qkv_mma() {
    extern __shared__ char smraw[];
    const uint32_t smb = smem_u32(smraw);
    const int side = blockIdx.z;
    const int m0 = blockIdx.y << 7, n0 = blockIdx.x << 7;

    const __half* Ag = g_xh + ((size_t)side << 22) + (size_t)m0 * 256;
    const __half* Bg = g_wh + (size_t)n0 * 256;

    float acc[4][4][4] = {};
    gemm_core<8>(Ag, Bg, 256, 256, smb, acc);

    const int tid = threadIdx.x, wid = tid >> 5, lane = tid & 31;
    const int wm = wid >> 2, wn = wid & 3;
    const int qr = lane >> 2, qc = lane & 3;

    const int z  = side * 4 + (m0 >> 12);
    const int pb = m0 & 4095;

    if (n0 < 512) {
        __half* dst = ((n0 >> 8) == 0 ? g_qh : g_kh) + ((size_t)z << 20);
        const int nloc = n0 & 255;
        #pragma unroll
        for (int i = 0; i < 4; i++) {
            int p = pb + wm * 64 + i * 16 + qr;
            #pragma unroll
            for (int j = 0; j < 4; j++) {
                int col = nloc + wn * 32 + j * 8 + qc * 2;
                *(__half2*)(dst + (size_t)p * 256 + col) =
                    __floats2half2_rn(acc[i][j][0], acc[i][j][1]);
                *(__half2*)(dst + (size_t)(p + 8) * 256 + col) =
                    __floats2half2_rn(acc[i][j][2], acc[i][j][3]);
            }
        }
    } else {
        // V: transpose via smem -> g_vth[z][c][m]
        __syncthreads();
        __half* st = (__half*)smraw;   // [128 n][136 m]
        #pragma unroll
        for (int i = 0; i < 4; i++) {
            int ml = wm * 64 + i * 16 + qr;
            #pragma unroll
            for (int j = 0; j < 4; j++) {
                int nl = wn * 32 + j * 8 + qc * 2;
                st[(size_t)nl * 136 + ml]           = __float2half_rn(acc[i][j][0]);
                st[(size_t)(nl + 1) * 136 + ml]     = __float2half_rn(acc[i][j][1]);
                st[(size_t)nl * 136 + ml + 8]       = __float2half_rn(acc[i][j][2]);
                st[(size_t)(nl + 1) * 136 + ml + 8] = __float2half_rn(acc[i][j][3]);
            }
        }
        __syncthreads();
        const int cv0 = n0 - 512;
        __half* dst = g_vth + ((size_t)z << 20) + pb;
        for (int idx = tid; idx < 128 * 16; idx += 256) {
            int r = idx >> 4, g = idx & 15;
            uint4 v = *(const uint4*)(st + (size_t)r * 136 + g * 8);
            *(uint4*)(dst + (size_t)(cv0 + r) * 4096 + g * 8) = v;
        }
    }
}

// ---------------------------------------------------------------------------
// Kernel 4: scores  E[z,m,n] = exp(scale * Q[z][m] . K[z'][n]) -> fp16
// grid (32, 32, 8)
// ---------------------------------------------------------------------------
__global__ __launch_bounds__(256, 2) void scores_mma() {
    extern __shared__ char smraw[];
    const uint32_t smb = smem_u32(smraw);
    const int z = blockIdx.z;
    const int zk = ((z >> 2) ^ 1) * 4 + (z & 3);
    const int m0 = blockIdx.y << 7, n0 = blockIdx.x << 7;

    const __half* Ag = g_qh + ((size_t)z << 20) + (size_t)m0 * 256;
    const __half* Bg = g_kh + ((size_t)zk << 20) + (size_t)n0 * 256;

    float acc[4][4][4] = {};
    gemm_core<8>(Ag, Bg, 256, 256, smb, acc);

    const int tid = threadIdx.x, wid = tid >> 5, lane = tid & 31;
    const int wm = wid >> 2, wn = wid & 3;
    const int qr = lane >> 2, qc = lane & 3;

    __half* Ce = g_eh + ((size_t)z << 24);
    const float scale = 0.0625f;
    #pragma unroll
    for (int i = 0; i < 4; i++) {
        int m = m0 + wm * 64 + i * 16 + qr;
        #pragma unroll
        for (int j = 0; j < 4; j++) {
            int n = n0 + wn * 32 + j * 8 + qc * 2;
            *(__half2*)(Ce + (size_t)m * 4096 + n) =
                __floats2half2_rn(__expf(acc[i][j][0] * scale),
                                  __expf(acc[i][j][1] * scale));
            *(__half2*)(Ce + (size_t)(m + 8) * 4096 + n) =
                __floats2half2_rn(__expf(acc[i][j][2] * scale),
                                  __expf(acc[i][j][3] * scale));
        }
    }
}

// ---------------------------------------------------------------------------
// Kernel 5: P = E / sum_b E, in place on g_eh
// ---------------------------------------------------------------------------
__global__ __launch_bounds__(256) void pnorm_kernel() {
    size_t gid = (size_t)blockIdx.x * 256 + threadIdx.x;
    int side = (int)(gid >> 21);
    size_t nm = (gid & 0x1FFFFFull) << 3;
    __half* base = g_eh + (((size_t)side * 4) << 24) + nm;

    uint4 e[BATCH];
    #pragma unroll
    for (int b = 0; b < BATCH; b++) e[b] = *(const uint4*)(base + ((size_t)b << 24));

    #pragma unroll
    for (int t = 0; t < 4; t++) {
        uint32_t* w0 = &((uint32_t*)&e[0])[t];
        uint32_t* w1 = &((uint32_t*)&e[1])[t];
        uint32_t* w2 = &((uint32_t*)&e[2])[t];
        uint32_t* w3 = &((uint32_t*)&e[3])[t];
        float2 f0 = __half22float2(*(__half2*)w0);
        float2 f1 = __half22float2(*(__half2*)w1);
        float2 f2 = __half22float2(*(__half2*)w2);
        float2 f3 = __half22float2(*(__half2*)w3);
        float rx = 1.0f / (f0.x + f1.x + f2.x + f3.x);
        float ry = 1.0f / (f0.y + f1.y + f2.y + f3.y);
        *(__half2*)w0 = __floats2half2_rn(f0.x * rx, f0.y * ry);
        *(__half2*)w1 = __floats2half2_rn(f1.x * rx, f1.y * ry);
        *(__half2*)w2 = __floats2half2_rn(f2.x * rx, f2.y * ry);
        *(__half2*)w3 = __floats2half2_rn(f3.x * rx, f3.y * ry);
    }
    #pragma unroll
    for (int b = 0; b < BATCH; b++) *(uint4*)(base + ((size_t)b << 24)) = e[b];
}

// ---------------------------------------------------------------------------
// Kernel 6: O[z] = P[z] @ V[z] -> fp16.  grid (2, 32, 8), K = 4096
// ---------------------------------------------------------------------------
__global__ __launch_bounds__(256, 2) void pv_mma() {
    extern __shared__ char smraw[];
    const uint32_t smb = smem_u32(smraw);
    const int z = blockIdx.z;
    const int m0 = blockIdx.y << 7, n0 = blockIdx.x << 7;

    const __half* Ag = g_eh  + ((size_t)z << 24) + (size_t)m0 * 4096;
    const __half* Bg = g_vth + ((size_t)z << 20) + (size_t)n0 * 4096;

    float acc[4][4][4] = {};
    gemm_core<128>(Ag, Bg, 4096, 4096, smb, acc);

    const int tid = threadIdx.x, wid = tid >> 5, lane = tid & 31;
    const int wm = wid >> 2, wn = wid & 3;
    const int qr = lane >> 2, qc = lane & 3;

    __half* Co = g_oh + ((size_t)z << 20);
    #pragma unroll
    for (int i = 0; i < 4; i++) {
        int m = m0 + wm * 64 + i * 16 + qr;
        #pragma unroll
        for (int j = 0; j < 4; j++) {
            int n = n0 + wn * 32 + j * 8 + qc * 2;
            *(__half2*)(Co + (size_t)m * 256 + n) =
                __floats2half2_rn(acc[i][j][0], acc[i][j][1]);
            *(__half2*)(Co + (size_t)(m + 8) * 256 + n) =
                __floats2half2_rn(acc[i][j][2], acc[i][j][3]);
        }
    }
}

// ---------------------------------------------------------------------------
// Kernel 7: out[b,c,p] = x[b,c,p] + (O @ Wo)[b,p,c]   (fp16 MMA + transpose)
// grid (2, 128, 2)
// ---------------------------------------------------------------------------
__global__ __launch_bounds__(256, 2) void out_mma(const float* __restrict__ xl,
                                                  const float* __restrict__ xr,
                                                  float* __restrict__ outp) {
    extern __shared__ char smraw[];
    const uint32_t smb = smem_u32(smraw);
    const int side = blockIdx.z;
    const int m0 = blockIdx.y << 7, n0 = blockIdx.x << 7;

    const __half* Ag = g_oh + ((size_t)side << 22) + (size_t)m0 * 256;
    const __half* Bg = g_wh + (size_t)(768 + n0) * 256;

    float acc[4][4][4] = {};
    gemm_core<8>(Ag, Bg, 256, 256, smb, acc);

    const int tid = threadIdx.x, wid = tid >> 5, lane = tid & 31;
    const int wm = wid >> 2, wn = wid & 3;
    const int qr = lane >> 2, qc = lane & 3;

    __syncthreads();
    float* st = (float*)smraw;   // [128 m][129]
    #pragma unroll
    for (int i = 0; i < 4; i++) {
        int ml = wm * 64 + i * 16 + qr;
        #pragma unroll
        for (int j = 0; j < 4; j++) {
            int nl = wn * 32 + j * 8 + qc * 2;
            st[(size_t)ml * 129 + nl]           = acc[i][j][0];
            st[(size_t)ml * 129 + nl + 1]       = acc[i][j][1];
            st[(size_t)(ml + 8) * 129 + nl]     = acc[i][j][2];
            st[(size_t)(ml + 8) * 129 + nl + 1] = acc[i][j][3];
        }
    }
    __syncthreads();

    const float* x = side ? xr : xl;
    float* op = outp + ((size_t)side << 22);
    const int b = m0 >> 12, p0 = m0 & 4095;
    for (int idx = tid; idx < 128 * 128; idx += 256) {
        int cl = idx >> 7, pl = idx & 127;
        size_t off = ((size_t)b * 256 + n0 + cl) * 4096 + p0 + pl;
        op[off] = x[off] + st[(size_t)pl * 129 + cl];
    }
}

// ---------------------------------------------------------------------------
extern "C" void kernel_launch(void* const* d_in, const int* in_sizes, int n_in,
                              void* d_out, int out_size) {
    const float* x_l = (const float*)d_in[0];
    const float* x_r = (const float*)d_in[1];
    const float* Wq  = (const float*)d_in[2];
    const float* Wk  = (const float*)d_in[3];
    const float* Wv  = (const float*)d_in[4];
    const float* Wo  = (const float*)d_in[5];
    const float* g1  = (const float*)d_in[6];
    const float* b1  = (const float*)d_in[7];
    const float* g2  = (const float*)d_in[8];
    const float* b2  = (const float*)d_in[9];
    float* out = (float*)d_out;

    cudaFuncSetAttribute(qkv_mma,    cudaFuncAttributeMaxDynamicSharedMemorySize, SMEM_MMA);
    cudaFuncSetAttribute(scores_mma, cudaFuncAttributeMaxDynamicSharedMemorySize, SMEM_MMA);
    cudaFuncSetAttribute(pv_mma,     cudaFuncAttributeMaxDynamicSharedMemorySize, SMEM_MMA);
    cudaFuncSetAttribute(out_mma,    cudaFuncAttributeMaxDynamicSharedMemorySize, SMEM_MMA);

    // 1) LayerNorm -> fp16 [p][c], weights -> fp16 [n][k]
    ln_kernel<<<dim3(HW / 32, BATCH), 256>>>(x_l, g1, b1, 0);
    ln_kernel<<<dim3(HW / 32, BATCH), 256>>>(x_r, g2, b2, 1);
    wconv_kernel<<<1024, 256>>>(Wq, Wk, Wv, Wo);

    // 2) fused QKV (V transposed)
    qkv_mma<<<dim3(6, 128, 2), 256, SMEM_MMA>>>();

    // 3) E = exp(scale * Q @ K^T)
    scores_mma<<<dim3(32, 32, 8), 256, SMEM_MMA>>>();

    // 4) P = E / sum_b E (in place)
    pnorm_kernel<<<16384, 256>>>();

    // 5) O = P @ V -> fp16
    pv_mma<<<dim3(2, 32, 8), 256, SMEM_MMA>>>();

    // 6) out = x + (O @ Wo)^T
    out_mma<<<dim3(2, 128, 2), 256, SMEM_MMA>>>(x_l, x_r, out);
}

// round 8
// speedup vs baseline: 1.2751x; 1.0478x over previous
#include <cuda_runtime.h>
#include <cuda_fp16.h>
#include <cstdint>

#define HW    4096
#define CH    256
#define BATCH 4

// fp16 operands / activations
__device__ __half g_xh [2ull * BATCH * HW * CH];          // LN output [side][p][c]
__device__ __half g_wh [1024ull * 256];                   // [Wq|Wk|Wv|Wo]^T: [n][k]
__device__ __half g_qh [2ull * BATCH * HW * CH];          // [z][p][c]
__device__ __half g_kh [2ull * BATCH * HW * CH];          // [z][p][c]
__device__ __half g_vth[2ull * BATCH * HW * CH];          // V^T: [z][c][m]
__device__ __half g_eh [2ull * BATCH * HW * HW];          // E then P (in place)
__device__ __half g_oh [2ull * BATCH * HW * CH];          // PV output fp16 [side][p][c]

// ---------------------------------------------------------------------------
// low-level helpers
// ---------------------------------------------------------------------------
__device__ __forceinline__ uint32_t smem_u32(const void* p) {
    uint32_t a;
    asm("{ .reg .u64 t; cvta.to.shared.u64 t, %1; cvt.u32.u64 %0, t; }"
        : "=r"(a) : "l"(p));
    return a;
}

__device__ __forceinline__ void mma16816(float (&c)[4], const uint32_t (&a)[4],
                                         uint32_t b0, uint32_t b1) {
    asm volatile(
        "mma.sync.aligned.m16n8k16.row.col.f32.f16.f16.f32 "
        "{%0,%1,%2,%3}, {%4,%5,%6,%7}, {%8,%9}, {%0,%1,%2,%3};"
        : "+f"(c[0]), "+f"(c[1]), "+f"(c[2]), "+f"(c[3])
        : "r"(a[0]), "r"(a[1]), "r"(a[2]), "r"(a[3]), "r"(b0), "r"(b1));
}

__device__ __forceinline__ void ldsm4(uint32_t (&r)[4], uint32_t addr) {
    asm volatile("ldmatrix.sync.aligned.m8n8.x4.shared.b16 {%0,%1,%2,%3}, [%4];"
        : "=r"(r[0]), "=r"(r[1]), "=r"(r[2]), "=r"(r[3]) : "r"(addr));
}

#define CP16(s, g) \
    asm volatile("cp.async.cg.shared.global [%0], [%1], 16;" :: "r"(s), "l"(g))
#define CP_COMMIT() asm volatile("cp.async.commit_group;")
#define CP_WAIT1()  asm volatile("cp.async.wait_group 1;")

// desync co-resident CTAs to break barrier phase-lock
__device__ __forceinline__ void desync() {
    unsigned bid = blockIdx.x + gridDim.x * (blockIdx.y + gridDim.y * blockIdx.z);
    unsigned ph = bid % 3u;
    if (ph) __nanosleep(ph * 600u);
}

// ---------------------------------------------------------------------------
// GEMM core: CTA 128x128, k-chunk 64 halfs, 3-stage cp.async pipeline,
// ldmatrix fragments. 256 threads = 8 warps (2m x 4n), warp tile 64x32.
// smem stage: (128 A rows + 128 B rows) x 144B = 36864 B; 3 stages = 108 KB.
// 2 CTAs/SM. One wait+sync per 64 k-steps; warp-staggered ks order.
// ---------------------------------------------------------------------------
#define STG_B    36864
#define SMEM_MMA 110592

template <int NCH>   // number of k32 chunks; must be even
__device__ __forceinline__ void gemm_core(const __half* __restrict__ Ag,
                                          const __half* __restrict__ Bg,
                                          int ldA, int ldB, uint32_t smb,
                                          float (&acc)[4][4][4]) {
    const int tid  = threadIdx.x;
    const int lane = tid & 31, wid = tid >> 5;
    const int wm = wid >> 2, wn = wid & 3;

    const int lr = tid >> 3;                 // load row 0..31
    const int lc = tid & 7;                  // 16B column 0..7
    const __half* agp = Ag + (size_t)lr * ldA + lc * 8;
    const __half* bgp = Bg + (size_t)lr * ldB + lc * 8;

    const uint32_t sA = smb + lr * 144 + lc * 16;
    const uint32_t sB = sA + 128 * 144;

    auto issue = [&](int s, int c64) {
        const uint32_t off = s * STG_B;
        const __half* a0 = agp + (size_t)c64 * 64;
        const __half* b0 = bgp + (size_t)c64 * 64;
        #pragma unroll
        for (int r = 0; r < 4; r++) {
            CP16(sA + off + r * 32 * 144, a0 + (size_t)(r * 32) * ldA);
            CP16(sB + off + r * 32 * 144, b0 + (size_t)(r * 32) * ldB);
        }
        CP_COMMIT();
    };

    issue(0, 0); issue(1, 1);

    const uint32_t aBase = smb + (wm * 64 + (lane & 15)) * 144 + (lane >> 4) * 16;
    const uint32_t bBase = smb + 128 * 144 +
        (wn * 32 + (lane & 7) + ((lane >> 4) << 3)) * 144 + ((lane >> 3) & 1) * 16;

    const int NC64 = NCH / 2;
    int stg = 0, nxt = 2;
    #pragma unroll 1
    for (int c = 0; c < NC64; c++) {
        CP_WAIT1();
        __syncthreads();
        const uint32_t off = stg * STG_B;
        if (c + 2 < NC64) issue(nxt, c + 2);
        else CP_COMMIT();                 // keep group count uniform
        if (++stg == 3) stg = 0;
        if (++nxt == 3) nxt = 0;
        #pragma unroll
        for (int k4 = 0; k4 < 4; k4++) {
            const int ks = (k4 + 2 * wm) & 3;   // stagger m-groups
            uint32_t af[4][4], bf[2][4];
            #pragma unroll
            for (int i = 0; i < 4; i++) ldsm4(af[i], aBase + off + i * 16 * 144 + ks * 32);
            #pragma unroll
            for (int p = 0; p < 2; p++) ldsm4(bf[p], bBase + off + p * 16 * 144 + ks * 32);
            #pragma unroll
            for (int i = 0; i < 4; i++)
                #pragma unroll
                for (int j = 0; j < 4; j++)
                    mma16816(acc[i][j], af[i], bf[j >> 1][(j & 1) * 2],
                             bf[j >> 1][(j & 1) * 2 + 1]);
        }
    }
}

// ---------------------------------------------------------------------------
// Kernel 1: LayerNorm over channels with transpose -> fp16 [side][p][c]
// ---------------------------------------------------------------------------
__global__ __launch_bounds__(256) void ln_kernel(const float* __restrict__ x,
                                                 const float* __restrict__ gm,
                                                 const float* __restrict__ bt,
                                                 int side) {
    int b  = blockIdx.y;
    int p0 = blockIdx.x << 5;
    int tid = threadIdx.x, lane = tid & 31, warp = tid >> 5;

    __shared__ float tile[CH][33];
    __shared__ float red[2][8][32];
    __shared__ float mu_s[32], rs_s[32];

    #pragma unroll 4
    for (int i = 0; i < 32; i++) {
        int c = (warp << 5) + i;
        tile[c][lane] = x[((size_t)b * CH + c) * HW + p0 + lane];
    }
    __syncthreads();

    {
        int pl = tid & 31, seg = tid >> 5;
        float s = 0.f, s2 = 0.f;
        #pragma unroll 8
        for (int c = seg * 32; c < seg * 32 + 32; c++) {
            float v = tile[c][pl];
            s += v; s2 += v * v;
        }
        red[0][seg][pl] = s;
        red[1][seg][pl] = s2;
    }
    __syncthreads();
    if (tid < 32) {
        float S = 0.f, S2 = 0.f;
        #pragma unroll
        for (int g = 0; g < 8; g++) { S += red[0][g][tid]; S2 += red[1][g][tid]; }
        float mu  = S * (1.f / 256.f);
        float var = S2 * (1.f / 256.f) - mu * mu;
        mu_s[tid] = mu;
        rs_s[tid] = rsqrtf(var + 1e-5f);
    }
    __syncthreads();

    __half* xh = g_xh + ((size_t)side << 22);
    #pragma unroll
    for (int pp = warp * 4; pp < warp * 4 + 4; pp++) {
        float mu = mu_s[pp], rs = rs_s[pp];
        #pragma unroll
        for (int c = lane; c < CH; c += 32) {
            float v = (tile[c][pp] - mu) * rs * gm[c] + bt[c];
            xh[((size_t)(b * HW + p0 + pp)) * 256 + c] = __float2half_rn(v);
        }
    }
}

// ---------------------------------------------------------------------------
// Kernel 2: weight transpose+convert: g_wh[n][k] = W[k][n], 4 matrices
// ---------------------------------------------------------------------------
__global__ __launch_bounds__(256) void wconv_kernel(const float* __restrict__ Wq,
                                                    const float* __restrict__ Wk,
                                                    const float* __restrict__ Wv,
                                                    const float* __restrict__ Wo) {
    int n = blockIdx.x, k = threadIdx.x;
    const float* W = (n < 256) ? Wq : (n < 512) ? Wk : (n < 768) ? Wv : Wo;
    g_wh[(size_t)n * 256 + k] = __float2half_rn(W[(size_t)k * 256 + (n & 255)]);
}

// ---------------------------------------------------------------------------
// Kernel 3: fused QKV GEMM. grid (6, 128, 2). N: [0,256)Q [256,512)K [512,768)V
// ---------------------------------------------------------------------------
__global__ __launch_bounds__(256, 2) void qkv_mma() {
    extern __shared__ char smraw[];
    const uint32_t smb = smem_u32(smraw);
    desync();
    const int side = blockIdx.z;
    const int m0 = blockIdx.y << 7, n0 = blockIdx.x << 7;

    const __half* Ag = g_xh + ((size_t)side << 22) + (size_t)m0 * 256;
    const __half* Bg = g_wh + (size_t)n0 * 256;

    float acc[4][4][4] = {};
    gemm_core<8>(Ag, Bg, 256, 256, smb, acc);

    const int tid = threadIdx.x, wid = tid >> 5, lane = tid & 31;
    const int wm = wid >> 2, wn = wid & 3;
    const int qr = lane >> 2, qc = lane & 3;

    const int z  = side * 4 + (m0 >> 12);
    const int pb = m0 & 4095;

    if (n0 < 512) {
        // stage through smem -> coalesced 16B stores
        __syncthreads();
        __half* st = (__half*)smraw;   // [128 m][136 pitch]
        #pragma unroll
        for (int i = 0; i < 4; i++) {
            int ml = wm * 64 + i * 16 + qr;
            #pragma unroll
            for (int j = 0; j < 4; j++) {
                int nl = wn * 32 + j * 8 + qc * 2;
                *(__half2*)(st + (size_t)ml * 136 + nl) =
                    __floats2half2_rn(acc[i][j][0], acc[i][j][1]);
                *(__half2*)(st + (size_t)(ml + 8) * 136 + nl) =
                    __floats2half2_rn(acc[i][j][2], acc[i][j][3]);
            }
        }
        __syncthreads();
        __half* dst = ((n0 >> 8) == 0 ? g_qh : g_kh) + ((size_t)z << 20);
        const int nloc = n0 & 255;
        for (int idx = tid; idx < 128 * 16; idx += 256) {
            int r = idx >> 4, g = idx & 15;
            *(uint4*)(dst + (size_t)(pb + r) * 256 + nloc + g * 8) =
                *(const uint4*)(st + (size_t)r * 136 + g * 8);
        }
    } else {
        // V: transpose via smem -> g_vth[z][c][m]
        __syncthreads();
        __half* st = (__half*)smraw;   // [128 n][136 m]
        #pragma unroll
        for (int i = 0; i < 4; i++) {
            int ml = wm * 64 + i * 16 + qr;
            #pragma unroll
            for (int j = 0; j < 4; j++) {
                int nl = wn * 32 + j * 8 + qc * 2;
                st[(size_t)nl * 136 + ml]           = __float2half_rn(acc[i][j][0]);
                st[(size_t)(nl + 1) * 136 + ml]     = __float2half_rn(acc[i][j][1]);
                st[(size_t)nl * 136 + ml + 8]       = __float2half_rn(acc[i][j][2]);
                st[(size_t)(nl + 1) * 136 + ml + 8] = __float2half_rn(acc[i][j][3]);
            }
        }
        __syncthreads();
        const int cv0 = n0 - 512;
        __half* dst = g_vth + ((size_t)z << 20) + pb;
        for (int idx = tid; idx < 128 * 16; idx += 256) {
            int r = idx >> 4, g = idx & 15;
            uint4 v = *(const uint4*)(st + (size_t)r * 136 + g * 8);
            *(uint4*)(dst + (size_t)(cv0 + r) * 4096 + g * 8) = v;
        }
    }
}

// ---------------------------------------------------------------------------
// Kernel 4: scores  E[z,m,n] = exp(scale * Q[z][m] . K[z'][n]) -> fp16
// grid (32, 32, 8)
// ---------------------------------------------------------------------------
__global__ __launch_bounds__(256, 2) void scores_mma() {
    extern __shared__ char smraw[];
    const uint32_t smb = smem_u32(smraw);
    desync();
    const int z = blockIdx.z;
    const int zk = ((z >> 2) ^ 1) * 4 + (z & 3);
    const int m0 = blockIdx.y << 7, n0 = blockIdx.x << 7;

    const __half* Ag = g_qh + ((size_t)z << 20) + (size_t)m0 * 256;
    const __half* Bg = g_kh + ((size_t)zk << 20) + (size_t)n0 * 256;

    float acc[4][4][4] = {};
    gemm_core<8>(Ag, Bg, 256, 256, smb, acc);

    const int tid = threadIdx.x, wid = tid >> 5, lane = tid & 31;
    const int wm = wid >> 2, wn = wid & 3;
    const int qr = lane >> 2, qc = lane & 3;

    const float scale = 0.0625f;
    // exp + stage through smem -> coalesced stores
    __syncthreads();
    __half* st = (__half*)smraw;   // [128 m][136 pitch]
    #pragma unroll
    for (int i = 0; i < 4; i++) {
        int ml = wm * 64 + i * 16 + qr;
        #pragma unroll
        for (int j = 0; j < 4; j++) {
            int nl = wn * 32 + j * 8 + qc * 2;
            *(__half2*)(st + (size_t)ml * 136 + nl) =
                __floats2half2_rn(__expf(acc[i][j][0] * scale),
                                  __expf(acc[i][j][1] * scale));
            *(__half2*)(st + (size_t)(ml + 8) * 136 + nl) =
                __floats2half2_rn(__expf(acc[i][j][2] * scale),
                                  __expf(acc[i][j][3] * scale));
        }
    }
    __syncthreads();
    __half* Ce = g_eh + ((size_t)z << 24);
    for (int idx = tid; idx < 128 * 16; idx += 256) {
        int r = idx >> 4, g = idx & 15;
        *(uint4*)(Ce + (size_t)(m0 + r) * 4096 + n0 + g * 8) =
            *(const uint4*)(st + (size_t)r * 136 + g * 8);
    }
}

// ---------------------------------------------------------------------------
// Kernel 5: P = E / sum_b E, in place on g_eh
// ---------------------------------------------------------------------------
__global__ __launch_bounds__(256) void pnorm_kernel() {
    size_t gid = (size_t)blockIdx.x * 256 + threadIdx.x;
    int side = (int)(gid >> 21);
    size_t nm = (gid & 0x1FFFFFull) << 3;
    __half* base = g_eh + (((size_t)side * 4) << 24) + nm;

    uint4 e[BATCH];
    #pragma unroll
    for (int b = 0; b < BATCH; b++) e[b] = *(const uint4*)(base + ((size_t)b << 24));

    #pragma unroll
    for (int t = 0; t < 4; t++) {
        uint32_t* w0 = &((uint32_t*)&e[0])[t];
        uint32_t* w1 = &((uint32_t*)&e[1])[t];
        uint32_t* w2 = &((uint32_t*)&e[2])[t];
        uint32_t* w3 = &((uint32_t*)&e[3])[t];
        float2 f0 = __half22float2(*(__half2*)w0);
        float2 f1 = __half22float2(*(__half2*)w1);
        float2 f2 = __half22float2(*(__half2*)w2);
        float2 f3 = __half22float2(*(__half2*)w3);
        float rx = 1.0f / (f0.x + f1.x + f2.x + f3.x);
        float ry = 1.0f / (f0.y + f1.y + f2.y + f3.y);
        *(__half2*)w0 = __floats2half2_rn(f0.x * rx, f0.y * ry);
        *(__half2*)w1 = __floats2half2_rn(f1.x * rx, f1.y * ry);
        *(__half2*)w2 = __floats2half2_rn(f2.x * rx, f2.y * ry);
        *(__half2*)w3 = __floats2half2_rn(f3.x * rx, f3.y * ry);
    }
    #pragma unroll
    for (int b = 0; b < BATCH; b++) *(uint4*)(base + ((size_t)b << 24)) = e[b];
}

// ---------------------------------------------------------------------------
// Kernel 6: O[z] = P[z] @ V[z] -> fp16.  grid (2, 32, 8), K = 4096
// ---------------------------------------------------------------------------
__global__ __launch_bounds__(256, 2) void pv_mma() {
    extern __shared__ char smraw[];
    const uint32_t smb = smem_u32(smraw);
    desync();
    const int z = blockIdx.z;
    const int m0 = blockIdx.y << 7, n0 = blockIdx.x << 7;

    const __half* Ag = g_eh  + ((size_t)z << 24) + (size_t)m0 * 4096;
    const __half* Bg = g_vth + ((size_t)z << 20) + (size_t)n0 * 4096;

    float acc[4][4][4] = {};
    gemm_core<128>(Ag, Bg, 4096, 4096, smb, acc);

    const int tid = threadIdx.x, wid = tid >> 5, lane = tid & 31;
    const int wm = wid >> 2, wn = wid & 3;
    const int qr = lane >> 2, qc = lane & 3;

    // stage through smem -> coalesced stores
    __syncthreads();
    __half* st = (__half*)smraw;   // [128 m][136 pitch]
    #pragma unroll
    for (int i = 0; i < 4; i++) {
        int ml = wm * 64 + i * 16 + qr;
        #pragma unroll
        for (int j = 0; j < 4; j++) {
            int nl = wn * 32 + j * 8 + qc * 2;
            *(__half2*)(st + (size_t)ml * 136 + nl) =
                __floats2half2_rn(acc[i][j][0], acc[i][j][1]);
            *(__half2*)(st + (size_t)(ml + 8) * 136 + nl) =
                __floats2half2_rn(acc[i][j][2], acc[i][j][3]);
        }
    }
    __syncthreads();
    __half* Co = g_oh + ((size_t)z << 20);
    for (int idx = tid; idx < 128 * 16; idx += 256) {
        int r = idx >> 4, g = idx & 15;
        *(uint4*)(Co + (size_t)(m0 + r) * 256 + n0 + g * 8) =
            *(const uint4*)(st + (size_t)r * 136 + g * 8);
    }
}

// ---------------------------------------------------------------------------
// Kernel 7: out[b,c,p] = x[b,c,p] + (O @ Wo)[b,p,c]   (fp16 MMA + transpose)
// grid (2, 128, 2)
// ---------------------------------------------------------------------------
__global__ __launch_bounds__(256, 2) void out_mma(const float* __restrict__ xl,
                                                  const float* __restrict__ xr,
                                                  float* __restrict__ outp) {
    extern __shared__ char smraw[];
    const uint32_t smb = smem_u32(smraw);
    const int side = blockIdx.z;
    const int m0 = blockIdx.y << 7, n0 = blockIdx.x << 7;

    const __half* Ag = g_oh + ((size_t)side << 22) + (size_t)m0 * 256;
    const __half* Bg = g_wh + (size_t)(768 + n0) * 256;

    float acc[4][4][4] = {};
    gemm_core<8>(Ag, Bg, 256, 256, smb, acc);

    const int tid = threadIdx.x, wid = tid >> 5, lane = tid & 31;
    const int wm = wid >> 2, wn = wid & 3;
    const int qr = lane >> 2, qc = lane & 3;

    __syncthreads();
    float* st = (float*)smraw;   // [128 m][129]
    #pragma unroll
    for (int i = 0; i < 4; i++) {
        int ml = wm * 64 + i * 16 + qr;
        #pragma unroll
        for (int j = 0; j < 4; j++) {
            int nl = wn * 32 + j * 8 + qc * 2;
            st[(size_t)ml * 129 + nl]           = acc[i][j][0];
            st[(size_t)ml * 129 + nl + 1]       = acc[i][j][1];
            st[(size_t)(ml + 8) * 129 + nl]     = acc[i][j][2];
            st[(size_t)(ml + 8) * 129 + nl + 1] = acc[i][j][3];
        }
    }
    __syncthreads();

    const float* x = side ? xr : xl;
    float* op = outp + ((size_t)side << 22);
    const int b = m0 >> 12, p0 = m0 & 4095;
    for (int idx = tid; idx < 128 * 128; idx += 256) {
        int cl = idx >> 7, pl = idx & 127;
        size_t off = ((size_t)b * 256 + n0 + cl) * 4096 + p0 + pl;
        op[off] = x[off] + st[(size_t)pl * 129 + cl];
    }
}

// ---------------------------------------------------------------------------
extern "C" void kernel_launch(void* const* d_in, const int* in_sizes, int n_in,
                              void* d_out, int out_size) {
    const float* x_l = (const float*)d_in[0];
    const float* x_r = (const float*)d_in[1];
    const float* Wq  = (const float*)d_in[2];
    const float* Wk  = (const float*)d_in[3];
    const float* Wv  = (const float*)d_in[4];
    const float* Wo  = (const float*)d_in[5];
    const float* g1  = (const float*)d_in[6];
    const float* b1  = (const float*)d_in[7];
    const float* g2  = (const float*)d_in[8];
    const float* b2  = (const float*)d_in[9];
    float* out = (float*)d_out;

    cudaFuncSetAttribute(qkv_mma,    cudaFuncAttributeMaxDynamicSharedMemorySize, SMEM_MMA);
    cudaFuncSetAttribute(scores_mma, cudaFuncAttributeMaxDynamicSharedMemorySize, SMEM_MMA);
    cudaFuncSetAttribute(pv_mma,     cudaFuncAttributeMaxDynamicSharedMemorySize, SMEM_MMA);
    cudaFuncSetAttribute(out_mma,    cudaFuncAttributeMaxDynamicSharedMemorySize, SMEM_MMA);

    // 1) LayerNorm -> fp16 [p][c], weights -> fp16 [n][k]
    ln_kernel<<<dim3(HW / 32, BATCH), 256>>>(x_l, g1, b1, 0);
    ln_kernel<<<dim3(HW / 32, BATCH), 256>>>(x_r, g2, b2, 1);
    wconv_kernel<<<1024, 256>>>(Wq, Wk, Wv, Wo);

    // 2) fused QKV (V transposed)
    qkv_mma<<<dim3(6, 128, 2), 256, SMEM_MMA>>>();

    // 3) E = exp(scale * Q @ K^T)
    scores_mma<<<dim3(32, 32, 8), 256, SMEM_MMA>>>();

    // 4) P = E / sum_b E (in place)
    pnorm_kernel<<<16384, 256>>>();

    // 5) O = P @ V -> fp16
    pv_mma<<<dim3(2, 32, 8), 256, SMEM_MMA>>>();

    // 6) out = x + (O @ Wo)^T
    out_mma<<<dim3(2, 128, 2), 256, SMEM_MMA>>>(x_l, x_r, out);
}

// round 9
// speedup vs baseline: 1.3188x; 1.0343x over previous
#include <cuda_runtime.h>
#include <cuda_fp16.h>
#include <cstdint>

#define HW    4096
#define CH    256
#define BATCH 4

// fp16 operands / activations
__device__ __half g_xh [2ull * BATCH * HW * CH];          // LN output [side][p][c]
__device__ __half g_wh [1024ull * 256];                   // [Wq|Wk|Wv|Wo]^T: [n][k]
__device__ __half g_qh [2ull * BATCH * HW * CH];          // [z][p][c]
__device__ __half g_kh [2ull * BATCH * HW * CH];          // [z][p][c]
__device__ __half g_vth[2ull * BATCH * HW * CH];          // V^T: [z][c][m]
__device__ __half g_eh [2ull * BATCH * HW * HW];          // E then P (in place)
__device__ __half g_oh [2ull * BATCH * HW * CH];          // PV output fp16 [side][p][c]

// ---------------------------------------------------------------------------
// low-level helpers
// ---------------------------------------------------------------------------
__device__ __forceinline__ uint32_t smem_u32(const void* p) {
    uint32_t a;
    asm("{ .reg .u64 t; cvta.to.shared.u64 t, %1; cvt.u32.u64 %0, t; }"
        : "=r"(a) : "l"(p));
    return a;
}

__device__ __forceinline__ void mma16816(float (&c)[4], const uint32_t (&a)[4],
                                         uint32_t b0, uint32_t b1) {
    asm volatile(
        "mma.sync.aligned.m16n8k16.row.col.f32.f16.f16.f32 "
        "{%0,%1,%2,%3}, {%4,%5,%6,%7}, {%8,%9}, {%0,%1,%2,%3};"
        : "+f"(c[0]), "+f"(c[1]), "+f"(c[2]), "+f"(c[3])
        : "r"(a[0]), "r"(a[1]), "r"(a[2]), "r"(a[3]), "r"(b0), "r"(b1));
}

__device__ __forceinline__ void ldsm4(uint32_t (&r)[4], uint32_t addr) {
    asm volatile("ldmatrix.sync.aligned.m8n8.x4.shared.b16 {%0,%1,%2,%3}, [%4];"
        : "=r"(r[0]), "=r"(r[1]), "=r"(r[2]), "=r"(r[3]) : "r"(addr));
}

#define CP16(s, g) \
    asm volatile("cp.async.cg.shared.global [%0], [%1], 16;" :: "r"(s), "l"(g))
#define CP_COMMIT() asm volatile("cp.async.commit_group;")
#define CP_WAIT1()  asm volatile("cp.async.wait_group 1;")

// desync co-resident CTAs to break barrier phase-lock
__device__ __forceinline__ void desync() {
    unsigned bid = blockIdx.x + gridDim.x * (blockIdx.y + gridDim.y * blockIdx.z);
    unsigned ph = bid % 3u;
    if (ph) __nanosleep(ph * 600u);
}

// ---------------------------------------------------------------------------
// GEMM core: CTA 128x128, k-chunk 64 halfs, 3-stage cp.async pipeline,
// ldmatrix fragments. 256 threads = 8 warps (2m x 4n), warp tile 64x32.
// smem stage: (128 A rows + 128 B rows) x 144B = 36864 B; 3 stages = 108 KB.
// 2 CTAs/SM. One wait+sync per 64 k-steps; warp-staggered ks order.
// ---------------------------------------------------------------------------
#define STG_B    36864
#define SMEM_MMA 110592

template <int NCH>   // number of k32 chunks; must be even
__device__ __forceinline__ void gemm_core(const __half* __restrict__ Ag,
                                          const __half* __restrict__ Bg,
                                          int ldA, int ldB, uint32_t smb,
                                          float (&acc)[4][4][4]) {
    const int tid  = threadIdx.x;
    const int lane = tid & 31, wid = tid >> 5;
    const int wm = wid >> 2, wn = wid & 3;

    const int lr = tid >> 3;                 // load row 0..31
    const int lc = tid & 7;                  // 16B column 0..7
    const __half* agp = Ag + (size_t)lr * ldA + lc * 8;
    const __half* bgp = Bg + (size_t)lr * ldB + lc * 8;

    const uint32_t sA = smb + lr * 144 + lc * 16;
    const uint32_t sB = sA + 128 * 144;

    auto issue = [&](int s, int c64) {
        const uint32_t off = s * STG_B;
        const __half* a0 = agp + (size_t)c64 * 64;
        const __half* b0 = bgp + (size_t)c64 * 64;
        #pragma unroll
        for (int r = 0; r < 4; r++) {
            CP16(sA + off + r * 32 * 144, a0 + (size_t)(r * 32) * ldA);
            CP16(sB + off + r * 32 * 144, b0 + (size_t)(r * 32) * ldB);
        }
        CP_COMMIT();
    };

    issue(0, 0); issue(1, 1);

    const uint32_t aBase = smb + (wm * 64 + (lane & 15)) * 144 + (lane >> 4) * 16;
    const uint32_t bBase = smb + 128 * 144 +
        (wn * 32 + (lane & 7) + ((lane >> 4) << 3)) * 144 + ((lane >> 3) & 1) * 16;

    const int NC64 = NCH / 2;
    int stg = 0, nxt = 2;
    #pragma unroll 1
    for (int c = 0; c < NC64; c++) {
        CP_WAIT1();
        __syncthreads();
        const uint32_t off = stg * STG_B;
        if (c + 2 < NC64) issue(nxt, c + 2);
        else CP_COMMIT();                 // keep group count uniform
        if (++stg == 3) stg = 0;
        if (++nxt == 3) nxt = 0;
        #pragma unroll
        for (int k4 = 0; k4 < 4; k4++) {
            const int ks = (k4 + 2 * wm) & 3;   // stagger m-groups
            uint32_t af[4][4], bf[2][4];
            #pragma unroll
            for (int i = 0; i < 4; i++) ldsm4(af[i], aBase + off + i * 16 * 144 + ks * 32);
            #pragma unroll
            for (int p = 0; p < 2; p++) ldsm4(bf[p], bBase + off + p * 16 * 144 + ks * 32);
            #pragma unroll
            for (int i = 0; i < 4; i++)
                #pragma unroll
                for (int j = 0; j < 4; j++)
                    mma16816(acc[i][j], af[i], bf[j >> 1][(j & 1) * 2],
                             bf[j >> 1][(j & 1) * 2 + 1]);
        }
    }
}

// ---------------------------------------------------------------------------
// Kernel 1: LayerNorm over channels with transpose -> fp16 [side][p][c]
// ---------------------------------------------------------------------------
__global__ __launch_bounds__(256) void ln_kernel(const float* __restrict__ x,
                                                 const float* __restrict__ gm,
                                                 const float* __restrict__ bt,
                                                 int side) {
    int b  = blockIdx.y;
    int p0 = blockIdx.x << 5;
    int tid = threadIdx.x, lane = tid & 31, warp = tid >> 5;

    __shared__ float tile[CH][33];
    __shared__ float red[2][8][32];
    __shared__ float mu_s[32], rs_s[32];

    #pragma unroll 4
    for (int i = 0; i < 32; i++) {
        int c = (warp << 5) + i;
        tile[c][lane] = x[((size_t)b * CH + c) * HW + p0 + lane];
    }
    __syncthreads();

    {
        int pl = tid & 31, seg = tid >> 5;
        float s = 0.f, s2 = 0.f;
        #pragma unroll 8
        for (int c = seg * 32; c < seg * 32 + 32; c++) {
            float v = tile[c][pl];
            s += v; s2 += v * v;
        }
        red[0][seg][pl] = s;
        red[1][seg][pl] = s2;
    }
    __syncthreads();
    if (tid < 32) {
        float S = 0.f, S2 = 0.f;
        #pragma unroll
        for (int g = 0; g < 8; g++) { S += red[0][g][tid]; S2 += red[1][g][tid]; }
        float mu  = S * (1.f / 256.f);
        float var = S2 * (1.f / 256.f) - mu * mu;
        mu_s[tid] = mu;
        rs_s[tid] = rsqrtf(var + 1e-5f);
    }
    __syncthreads();

    __half* xh = g_xh + ((size_t)side << 22);
    #pragma unroll
    for (int pp = warp * 4; pp < warp * 4 + 4; pp++) {
        float mu = mu_s[pp], rs = rs_s[pp];
        #pragma unroll
        for (int c = lane; c < CH; c += 32) {
            float v = (tile[c][pp] - mu) * rs * gm[c] + bt[c];
            xh[((size_t)(b * HW + p0 + pp)) * 256 + c] = __float2half_rn(v);
        }
    }
}

// ---------------------------------------------------------------------------
// Kernel 2: weight transpose+convert: g_wh[n][k] = W[k][n], 4 matrices
// ---------------------------------------------------------------------------
__global__ __launch_bounds__(256) void wconv_kernel(const float* __restrict__ Wq,
                                                    const float* __restrict__ Wk,
                                                    const float* __restrict__ Wv,
                                                    const float* __restrict__ Wo) {
    int n = blockIdx.x, k = threadIdx.x;
    const float* W = (n < 256) ? Wq : (n < 512) ? Wk : (n < 768) ? Wv : Wo;
    g_wh[(size_t)n * 256 + k] = __float2half_rn(W[(size_t)k * 256 + (n & 255)]);
}

// ---------------------------------------------------------------------------
// Kernel 3: fused QKV GEMM. grid (6, 128, 2). N: [0,256)Q [256,512)K [512,768)V
// ---------------------------------------------------------------------------
__global__ __launch_bounds__(256, 2) void qkv_mma() {
    extern __shared__ char smraw[];
    const uint32_t smb = smem_u32(smraw);
    desync();
    const int side = blockIdx.z;
    const int m0 = blockIdx.y << 7, n0 = blockIdx.x << 7;

    const __half* Ag = g_xh + ((size_t)side << 22) + (size_t)m0 * 256;
    const __half* Bg = g_wh + (size_t)n0 * 256;

    float acc[4][4][4] = {};
    gemm_core<8>(Ag, Bg, 256, 256, smb, acc);

    const int tid = threadIdx.x, wid = tid >> 5, lane = tid & 31;
    const int wm = wid >> 2, wn = wid & 3;
    const int qr = lane >> 2, qc = lane & 3;

    const int z  = side * 4 + (m0 >> 12);
    const int pb = m0 & 4095;

    if (n0 < 512) {
        // stage through smem -> coalesced 16B stores
        __syncthreads();
        __half* st = (__half*)smraw;   // [128 m][136 pitch]
        #pragma unroll
        for (int i = 0; i < 4; i++) {
            int ml = wm * 64 + i * 16 + qr;
            #pragma unroll
            for (int j = 0; j < 4; j++) {
                int nl = wn * 32 + j * 8 + qc * 2;
                *(__half2*)(st + (size_t)ml * 136 + nl) =
                    __floats2half2_rn(acc[i][j][0], acc[i][j][1]);
                *(__half2*)(st + (size_t)(ml + 8) * 136 + nl) =
                    __floats2half2_rn(acc[i][j][2], acc[i][j][3]);
            }
        }
        __syncthreads();
        __half* dst = ((n0 >> 8) == 0 ? g_qh : g_kh) + ((size_t)z << 20);
        const int nloc = n0 & 255;
        for (int idx = tid; idx < 128 * 16; idx += 256) {
            int r = idx >> 4, g = idx & 15;
            *(uint4*)(dst + (size_t)(pb + r) * 256 + nloc + g * 8) =
                *(const uint4*)(st + (size_t)r * 136 + g * 8);
        }
    } else {
        // V: transpose via smem -> g_vth[z][c][m]
        __syncthreads();
        __half* st = (__half*)smraw;   // [128 n][136 m]
        #pragma unroll
        for (int i = 0; i < 4; i++) {
            int ml = wm * 64 + i * 16 + qr;
            #pragma unroll
            for (int j = 0; j < 4; j++) {
                int nl = wn * 32 + j * 8 + qc * 2;
                st[(size_t)nl * 136 + ml]           = __float2half_rn(acc[i][j][0]);
                st[(size_t)(nl + 1) * 136 + ml]     = __float2half_rn(acc[i][j][1]);
                st[(size_t)nl * 136 + ml + 8]       = __float2half_rn(acc[i][j][2]);
                st[(size_t)(nl + 1) * 136 + ml + 8] = __float2half_rn(acc[i][j][3]);
            }
        }
        __syncthreads();
        const int cv0 = n0 - 512;
        __half* dst = g_vth + ((size_t)z << 20) + pb;
        for (int idx = tid; idx < 128 * 16; idx += 256) {
            int r = idx >> 4, g = idx & 15;
            uint4 v = *(const uint4*)(st + (size_t)r * 136 + g * 8);
            *(uint4*)(dst + (size_t)(cv0 + r) * 4096 + g * 8) = v;
        }
    }
}

// ---------------------------------------------------------------------------
// Kernel 4 (FUSED scores + softmax-normalize):
//   For its (m0,n0,side) tile, one CTA computes E_b = exp(scale*Q_b.K'_b^T)
//   for ALL 4 batches (one continuous 16-chunk cp.async pipeline), writes
//   each E_b tile, then normalizes its own 4 tiles in place:
//   P_b = E_b / sum_b E_b  (reads are L2 hits of its own fresh writes).
// grid (32, 32, 2)
// ---------------------------------------------------------------------------
__global__ __launch_bounds__(256, 2) void scores_mma() {
    extern __shared__ char smraw[];
    const uint32_t smb = smem_u32(smraw);
    desync();
    const int side = blockIdx.z;
    const int m0 = blockIdx.y << 7, n0 = blockIdx.x << 7;

    const int tid = threadIdx.x, lane = tid & 31, wid = tid >> 5;
    const int wm = wid >> 2, wn = wid & 3;
    const int qr = lane >> 2, qc = lane & 3;

    const int lr = tid >> 3, lc = tid & 7;
    const size_t aoff = (size_t)(m0 + lr) * 256 + lc * 8;
    const size_t boff = (size_t)(n0 + lr) * 256 + lc * 8;
    const __half* qbase = g_qh + ((size_t)(side * 4) << 20);
    const __half* kbase = g_kh + ((size_t)((side ^ 1) * 4) << 20);

    const uint32_t sA = smb + lr * 144 + lc * 16;
    const uint32_t sB = sA + 128 * 144;

    auto issue = [&](int s, int c) {
        const uint32_t off = s * STG_B;
        const int b = c >> 2, ko = (c & 3) << 6;
        const __half* a0 = qbase + ((size_t)b << 20) + aoff + ko;
        const __half* b0 = kbase + ((size_t)b << 20) + boff + ko;
        #pragma unroll
        for (int r = 0; r < 4; r++) {
            CP16(sA + off + r * 32 * 144, a0 + (size_t)(r * 32) * 256);
            CP16(sB + off + r * 32 * 144, b0 + (size_t)(r * 32) * 256);
        }
        CP_COMMIT();
    };

    issue(0, 0); issue(1, 1);

    const uint32_t aBase = smb + (wm * 64 + (lane & 15)) * 144 + (lane >> 4) * 16;
    const uint32_t bBase = smb + 128 * 144 +
        (wn * 32 + (lane & 7) + ((lane >> 4) << 3)) * 144 + ((lane >> 3) & 1) * 16;

    const float scale = 0.0625f;
    float acc[4][4][4];

    int stg = 0, nxt = 2;
    #pragma unroll 1
    for (int c = 0; c < 16; c++) {
        CP_WAIT1();
        __syncthreads();      // also orders previous epilogue's smem use vs reuse
        const uint32_t off = stg * STG_B;
        if (c + 2 < 16) issue(nxt, c + 2);
        else CP_COMMIT();                 // keep group count uniform
        if (++stg == 3) stg = 0;
        if (++nxt == 3) nxt = 0;

        if ((c & 3) == 0) {
            #pragma unroll
            for (int i = 0; i < 4; i++)
                #pragma unroll
                for (int j = 0; j < 4; j++)
                    #pragma unroll
                    for (int t = 0; t < 4; t++) acc[i][j][t] = 0.f;
        }

        #pragma unroll
        for (int k4 = 0; k4 < 4; k4++) {
            const int ks = (k4 + 2 * wm) & 3;   // stagger m-groups
            uint32_t af[4][4], bf[2][4];
            #pragma unroll
            for (int i = 0; i < 4; i++) ldsm4(af[i], aBase + off + i * 16 * 144 + ks * 32);
            #pragma unroll
            for (int p = 0; p < 2; p++) ldsm4(bf[p], bBase + off + p * 16 * 144 + ks * 32);
            #pragma unroll
            for (int i = 0; i < 4; i++)
                #pragma unroll
                for (int j = 0; j < 4; j++)
                    mma16816(acc[i][j], af[i], bf[j >> 1][(j & 1) * 2],
                             bf[j >> 1][(j & 1) * 2 + 1]);
        }

        if ((c & 3) == 3) {
            // epilogue for batch b: exp + stage into the just-freed pipe stage
            const int b = c >> 2;
            const int fs = c % 3;          // stage consumed this iteration
            __half* stb = (__half*)(smraw + fs * STG_B);   // [128 m][136 pitch]
            __syncthreads();               // all warps done with stage fs
            #pragma unroll
            for (int i = 0; i < 4; i++) {
                int ml = wm * 64 + i * 16 + qr;
                #pragma unroll
                for (int j = 0; j < 4; j++) {
                    int nl = wn * 32 + j * 8 + qc * 2;
                    *(__half2*)(stb + (size_t)ml * 136 + nl) =
                        __floats2half2_rn(__expf(acc[i][j][0] * scale),
                                          __expf(acc[i][j][1] * scale));
                    *(__half2*)(stb + (size_t)(ml + 8) * 136 + nl) =
                        __floats2half2_rn(__expf(acc[i][j][2] * scale),
                                          __expf(acc[i][j][3] * scale));
                }
            }
            __syncthreads();
            __half* Ce = g_eh + ((size_t)(side * 4 + b) << 24);
            for (int idx = tid; idx < 128 * 16; idx += 256) {
                int r = idx >> 4, g = idx & 15;
                *(uint4*)(Ce + (size_t)(m0 + r) * 4096 + n0 + g * 8) =
                    *(const uint4*)(stb + (size_t)r * 136 + g * 8);
            }
            // next iteration's top __syncthreads orders these stores before
            // the cp.async that reuses stage fs.
        }
    }

    // in-place normalize: P_b = E_b / sum_b E_b over this CTA's own 4 tiles
    __syncthreads();   // CTA-scope visibility of all E writes (same-SM L1)
    __half* Eb = g_eh + ((size_t)(side * 4) << 24);
    #pragma unroll 1
    for (int s8 = 0; s8 < 8; s8++) {
        int idx = s8 * 256 + tid;
        int r = idx >> 4, g = idx & 15;
        __half* p = Eb + (size_t)(m0 + r) * 4096 + n0 + g * 8;
        uint4 e0 = *(const uint4*)(p);
        uint4 e1 = *(const uint4*)(p + (1ull << 24));
        uint4 e2 = *(const uint4*)(p + (2ull << 24));
        uint4 e3 = *(const uint4*)(p + (3ull << 24));
        #pragma unroll
        for (int t = 0; t < 4; t++) {
            float2 f0 = __half22float2(((const __half2*)&e0)[t]);
            float2 f1 = __half22float2(((const __half2*)&e1)[t]);
            float2 f2 = __half22float2(((const __half2*)&e2)[t]);
            float2 f3 = __half22float2(((const __half2*)&e3)[t]);
            float rx = 1.0f / (f0.x + f1.x + f2.x + f3.x);
            float ry = 1.0f / (f0.y + f1.y + f2.y + f3.y);
            ((__half2*)&e0)[t] = __floats2half2_rn(f0.x * rx, f0.y * ry);
            ((__half2*)&e1)[t] = __floats2half2_rn(f1.x * rx, f1.y * ry);
            ((__half2*)&e2)[t] = __floats2half2_rn(f2.x * rx, f2.y * ry);
            ((__half2*)&e3)[t] = __floats2half2_rn(f3.x * rx, f3.y * ry);
        }
        *(uint4*)(p)                = e0;
        *(uint4*)(p + (1ull << 24)) = e1;
        *(uint4*)(p + (2ull << 24)) = e2;
        *(uint4*)(p + (3ull << 24)) = e3;
    }
}

// ---------------------------------------------------------------------------
// Kernel 5: O[z] = P[z] @ V[z] -> fp16.  grid (2, 32, 8), K = 4096
// ---------------------------------------------------------------------------
__global__ __launch_bounds__(256, 2) void pv_mma() {
    extern __shared__ char smraw[];
    const uint32_t smb = smem_u32(smraw);
    desync();
    const int z = blockIdx.z;
    const int m0 = blockIdx.y << 7, n0 = blockIdx.x << 7;

    const __half* Ag = g_eh  + ((size_t)z << 24) + (size_t)m0 * 4096;
    const __half* Bg = g_vth + ((size_t)z << 20) + (size_t)n0 * 4096;

    float acc[4][4][4] = {};
    gemm_core<128>(Ag, Bg, 4096, 4096, smb, acc);

    const int tid = threadIdx.x, wid = tid >> 5, lane = tid & 31;
    const int wm = wid >> 2, wn = wid & 3;
    const int qr = lane >> 2, qc = lane & 3;

    // stage through smem -> coalesced stores
    __syncthreads();
    __half* st = (__half*)smraw;   // [128 m][136 pitch]
    #pragma unroll
    for (int i = 0; i < 4; i++) {
        int ml = wm * 64 + i * 16 + qr;
        #pragma unroll
        for (int j = 0; j < 4; j++) {
            int nl = wn * 32 + j * 8 + qc * 2;
            *(__half2*)(st + (size_t)ml * 136 + nl) =
                __floats2half2_rn(acc[i][j][0], acc[i][j][1]);
            *(__half2*)(st + (size_t)(ml + 8) * 136 + nl) =
                __floats2half2_rn(acc[i][j][2], acc[i][j][3]);
        }
    }
    __syncthreads();
    __half* Co = g_oh + ((size_t)z << 20);
    for (int idx = tid; idx < 128 * 16; idx += 256) {
        int r = idx >> 4, g = idx & 15;
        *(uint4*)(Co + (size_t)(m0 + r) * 256 + n0 + g * 8) =
            *(const uint4*)(st + (size_t)r * 136 + g * 8);
    }
}

// ---------------------------------------------------------------------------
// Kernel 6: out[b,c,p] = x[b,c,p] + (O @ Wo)[b,p,c]   (fp16 MMA + transpose)
// grid (2, 128, 2)
// ---------------------------------------------------------------------------
__global__ __launch_bounds__(256, 2) void out_mma(const float* __restrict__ xl,
                                                  const float* __restrict__ xr,
                                                  float* __restrict__ outp) {
    extern __shared__ char smraw[];
    const uint32_t smb = smem_u32(smraw);
    const int side = blockIdx.z;
    const int m0 = blockIdx.y << 7, n0 = blockIdx.x << 7;

    const __half* Ag = g_oh + ((size_t)side << 22) + (size_t)m0 * 256;
    const __half* Bg = g_wh + (size_t)(768 + n0) * 256;

    float acc[4][4][4] = {};
    gemm_core<8>(Ag, Bg, 256, 256, smb, acc);

    const int tid = threadIdx.x, wid = tid >> 5, lane = tid & 31;
    const int wm = wid >> 2, wn = wid & 3;
    const int qr = lane >> 2, qc = lane & 3;

    __syncthreads();
    float* st = (float*)smraw;   // [128 m][129]
    #pragma unroll
    for (int i = 0; i < 4; i++) {
        int ml = wm * 64 + i * 16 + qr;
        #pragma unroll
        for (int j = 0; j < 4; j++) {
            int nl = wn * 32 + j * 8 + qc * 2;
            st[(size_t)ml * 129 + nl]           = acc[i][j][0];
            st[(size_t)ml * 129 + nl + 1]       = acc[i][j][1];
            st[(size_t)(ml + 8) * 129 + nl]     = acc[i][j][2];
            st[(size_t)(ml + 8) * 129 + nl + 1] = acc[i][j][3];
        }
    }
    __syncthreads();

    const float* x = side ? xr : xl;
    float* op = outp + ((size_t)side << 22);
    const int b = m0 >> 12, p0 = m0 & 4095;
    for (int idx = tid; idx < 128 * 128; idx += 256) {
        int cl = idx >> 7, pl = idx & 127;
        size_t off = ((size_t)b * 256 + n0 + cl) * 4096 + p0 + pl;
        op[off] = x[off] + st[(size_t)pl * 129 + cl];
    }
}

// ---------------------------------------------------------------------------
extern "C" void kernel_launch(void* const* d_in, const int* in_sizes, int n_in,
                              void* d_out, int out_size) {
    const float* x_l = (const float*)d_in[0];
    const float* x_r = (const float*)d_in[1];
    const float* Wq  = (const float*)d_in[2];
    const float* Wk  = (const float*)d_in[3];
    const float* Wv  = (const float*)d_in[4];
    const float* Wo  = (const float*)d_in[5];
    const float* g1  = (const float*)d_in[6];
    const float* b1  = (const float*)d_in[7];
    const float* g2  = (const float*)d_in[8];
    const float* b2  = (const float*)d_in[9];
    float* out = (float*)d_out;

    cudaFuncSetAttribute(qkv_mma,    cudaFuncAttributeMaxDynamicSharedMemorySize, SMEM_MMA);
    cudaFuncSetAttribute(scores_mma, cudaFuncAttributeMaxDynamicSharedMemorySize, SMEM_MMA);
    cudaFuncSetAttribute(pv_mma,     cudaFuncAttributeMaxDynamicSharedMemorySize, SMEM_MMA);
    cudaFuncSetAttribute(out_mma,    cudaFuncAttributeMaxDynamicSharedMemorySize, SMEM_MMA);

    // 1) LayerNorm -> fp16 [p][c], weights -> fp16 [n][k]
    ln_kernel<<<dim3(HW / 32, BATCH), 256>>>(x_l, g1, b1, 0);
    ln_kernel<<<dim3(HW / 32, BATCH), 256>>>(x_r, g2, b2, 1);
    wconv_kernel<<<1024, 256>>>(Wq, Wk, Wv, Wo);

    // 2) fused QKV (V transposed)
    qkv_mma<<<dim3(6, 128, 2), 256, SMEM_MMA>>>();

    // 3) fused scores + batch-softmax normalize (writes P in place)
    scores_mma<<<dim3(32, 32, 2), 256, SMEM_MMA>>>();

    // 4) O = P @ V -> fp16
    pv_mma<<<dim3(2, 32, 8), 256, SMEM_MMA>>>();

    // 5) out = x + (O @ Wo)^T
    out_mma<<<dim3(2, 128, 2), 256, SMEM_MMA>>>(x_l, x_r, out);
}